// round 1
// baseline (speedup 1.0000x reference)
#include <cuda_runtime.h>
#include <math.h>

#define BATCH 4
#define C64   64
#define HW    65536
#define HEADS 4
#define HID   128
#define EPSF  1e-5f

#define TOT (BATCH*C64*HW)

// ---------------- scratch (device globals; no allocs) ----------------
__device__ float g_ni[TOT];
__device__ float g_ne[TOT];
__device__ float g_nc[TOT];
__device__ float g_nd[TOT];
// gram slots: 0=cc 1=ii 2=ee 3=ci 4=ce 5=dd 6=di 7=de ; each [BATCH][64][64]
__device__ float g_gram[8*BATCH*C64*C64];
// per batch: 0=M_c, 1=M_id, 2=M_ed
__device__ float g_M[BATCH*3*C64*C64];

// =====================================================================
// K1: channel LayerNorm for ni/ne/nc/nd  (+ zero gram accumulators)
// grid: BATCH*(HW/256), block 256 (1 thread = 1 pixel)
// =====================================================================
__global__ void __launch_bounds__(256) ln_kernel(
    const float* __restrict__ img, const float* __restrict__ evt,
    const float* __restrict__ wi, const float* __restrict__ bi,
    const float* __restrict__ we, const float* __restrict__ be,
    const float* __restrict__ wc, const float* __restrict__ bc,
    const float* __restrict__ wd, const float* __restrict__ bd)
{
    // zero gram accumulators (131072 floats) with first 128 blocks
    if (blockIdx.x < 128) {
        int base = blockIdx.x * 1024 + threadIdx.x * 4;
        g_gram[base+0] = 0.f; g_gram[base+1] = 0.f;
        g_gram[base+2] = 0.f; g_gram[base+3] = 0.f;
    }
    int b  = blockIdx.x >> 8;              // HW/256 = 256 blocks per batch
    int p  = ((blockIdx.x & 255) << 8) + threadIdx.x;
    const float* ip = img + (size_t)b*C64*HW + p;
    const float* ep = evt + (size_t)b*C64*HW + p;

    float si=0.f, se=0.f, sii=0.f, see=0.f, sie=0.f;
    #pragma unroll 8
    for (int c=0;c<C64;c++){
        float iv = ip[c*HW], ev = ep[c*HW];
        si += iv; se += ev; sii += iv*iv; see += ev*ev; sie += iv*ev;
    }
    const float inv64 = 1.f/64.f;
    float mi = si*inv64, me = se*inv64;
    float vi = sii*inv64 - mi*mi;
    float ve = see*inv64 - me*me;
    float mc = (si+se)*inv64, md = (si-se)*inv64;
    float vc = (sii + 2.f*sie + see)*inv64 - mc*mc;
    float vd = (sii - 2.f*sie + see)*inv64 - md*md;
    float ri = rsqrtf(vi+EPSF), re = rsqrtf(ve+EPSF);
    float rc = rsqrtf(vc+EPSF), rd = rsqrtf(vd+EPSF);

    size_t ob = (size_t)b*C64*HW + p;
    #pragma unroll 8
    for (int c=0;c<C64;c++){
        float iv = ip[c*HW], ev = ep[c*HW];
        g_ni[ob + (size_t)c*HW] = (iv-mi)*ri*wi[c] + bi[c];
        g_ne[ob + (size_t)c*HW] = (ev-me)*re*we[c] + be[c];
        g_nc[ob + (size_t)c*HW] = (iv+ev-mc)*rc*wc[c] + bc[c];
        g_nd[ob + (size_t)c*HW] = (iv-ev-md)*rd*wd[c] + bd[c];
    }
}

// =====================================================================
// K2: Gram blocks G = X @ Y^T (sum over pixels), 8 pairs x 4 batches.
// grid: (32 chunks, 8 pairs, 4 batches), block 256, 2048 px per chunk
// =====================================================================
__global__ void __launch_bounds__(256) gram_kernel()
{
    __shared__ float Xs[32][72];
    __shared__ float Ys[32][72];
    const int px_[8] = {2,0,1,2,2,3,3,3};   // 0=ni 1=ne 2=nc 3=nd
    const int py_[8] = {2,0,1,0,1,3,0,1};
    int pr = blockIdx.y, b = blockIdx.z;
    const float* tens[4] = {g_ni, g_ne, g_nc, g_nd};
    const float* X = tens[px_[pr]] + (size_t)b*C64*HW + blockIdx.x*2048;
    const float* Y = tens[py_[pr]] + (size_t)b*C64*HW + blockIdx.x*2048;

    int tid = threadIdx.x;
    int ty = tid >> 4, tx = tid & 15;
    int la = tid >> 2, lk = (tid & 3) * 8;

    float acc[4][4] = {};
    for (int k0 = 0; k0 < 2048; k0 += 32) {
        __syncthreads();
        float4 a0 = *(const float4*)&X[(size_t)la*HW + k0 + lk];
        float4 a1 = *(const float4*)&X[(size_t)la*HW + k0 + lk + 4];
        float4 b0 = *(const float4*)&Y[(size_t)la*HW + k0 + lk];
        float4 b1 = *(const float4*)&Y[(size_t)la*HW + k0 + lk + 4];
        Xs[lk+0][la]=a0.x; Xs[lk+1][la]=a0.y; Xs[lk+2][la]=a0.z; Xs[lk+3][la]=a0.w;
        Xs[lk+4][la]=a1.x; Xs[lk+5][la]=a1.y; Xs[lk+6][la]=a1.z; Xs[lk+7][la]=a1.w;
        Ys[lk+0][la]=b0.x; Ys[lk+1][la]=b0.y; Ys[lk+2][la]=b0.z; Ys[lk+3][la]=b0.w;
        Ys[lk+4][la]=b1.x; Ys[lk+5][la]=b1.y; Ys[lk+6][la]=b1.z; Ys[lk+7][la]=b1.w;
        __syncthreads();
        #pragma unroll 8
        for (int kk=0; kk<32; kk++){
            float4 av = *(const float4*)&Xs[kk][ty*4];
            float4 bv = *(const float4*)&Ys[kk][tx*4];
            float a4[4] = {av.x,av.y,av.z,av.w};
            float b4[4] = {bv.x,bv.y,bv.z,bv.w};
            #pragma unroll
            for (int ii=0;ii<4;ii++)
                #pragma unroll
                for (int jj=0;jj<4;jj++)
                    acc[ii][jj] += a4[ii]*b4[jj];
        }
    }
    float* G = g_gram + ((size_t)pr*BATCH + b)*C64*C64;
    #pragma unroll
    for (int ii=0;ii<4;ii++)
        #pragma unroll
        for (int jj=0;jj<4;jj++)
            atomicAdd(&G[(ty*4+ii)*C64 + tx*4+jj], acc[ii][jj]);
}

// =====================================================================
// K3: tiny per-batch math -> M_c, M_id, M_ed. grid 4, block 256.
// =====================================================================
__device__ __forceinline__ void ld_mat(float* s, const float* __restrict__ g, int tid){
    for (int i=tid; i<4096; i+=256) s[i] = g[i];
}
// C = A @ B  (64x64, row-major, no aliasing). Syncs after write.
__device__ __forceinline__ void mm64_nn(float* Cm, const float* A, const float* Bm, int tid){
    int ty = tid>>4, tx = tid&15;
    float acc[4][4] = {};
    for (int k=0;k<64;k++){
        float4 bv = *(const float4*)&Bm[k*64 + tx*4];
        float b4[4] = {bv.x,bv.y,bv.z,bv.w};
        #pragma unroll
        for (int ii=0;ii<4;ii++){
            float a = A[(ty*4+ii)*64 + k];
            #pragma unroll
            for (int jj=0;jj<4;jj++) acc[ii][jj] += a*b4[jj];
        }
    }
    #pragma unroll
    for (int ii=0;ii<4;ii++)
        #pragma unroll
        for (int jj=0;jj<4;jj++)
            Cm[(ty*4+ii)*64 + tx*4+jj] = acc[ii][jj];
    __syncthreads();
}
// C = A @ B^T
__device__ __forceinline__ void mm64_nt(float* Cm, const float* A, const float* Bm, int tid){
    int ty = tid>>4, tx = tid&15;
    float acc[4][4] = {};
    for (int k=0;k<64;k++){
        float a4[4], b4[4];
        #pragma unroll
        for (int ii=0;ii<4;ii++) a4[ii] = A[(ty*4+ii)*64 + k];
        #pragma unroll
        for (int jj=0;jj<4;jj++) b4[jj] = Bm[(tx*4+jj)*64 + k];
        #pragma unroll
        for (int ii=0;ii<4;ii++)
            #pragma unroll
            for (int jj=0;jj<4;jj++) acc[ii][jj] += a4[ii]*b4[jj];
    }
    #pragma unroll
    for (int ii=0;ii<4;ii++)
        #pragma unroll
        for (int jj=0;jj<4;jj++)
            Cm[(ty*4+ii)*64 + tx*4+jj] = acc[ii][jj];
    __syncthreads();
}
// inv[r] = 1/max(sqrt(dot(T[r],W[r])),1e-12)
__device__ __forceinline__ void rownorm_inv(float* inv, const float* T, const float* Wm, int tid){
    if (tid < 64){
        float s = 0.f;
        for (int k=0;k<64;k++) s += T[tid*64+k]*Wm[tid*64+k];
        inv[tid] = 1.f / fmaxf(sqrtf(fmaxf(s, 0.f)), 1e-12f);
    }
    __syncthreads();
}
// out[64][16]: softmax over 16 keys within head of normalized logits
__device__ __forceinline__ void attn_softmax(float* out, const float* raw,
        const float* invq, const float* invk, const float* __restrict__ temp, int tid){
    if (tid < 64){
        int head = tid >> 4, base = head*16;
        float t = temp[head];
        float l[16]; float mx = -1e30f;
        #pragma unroll
        for (int s=0;s<16;s++){
            l[s] = raw[tid*64 + base + s] * invq[tid] * invk[base+s] * t;
            mx = fmaxf(mx, l[s]);
        }
        float sum = 0.f;
        #pragma unroll
        for (int s=0;s<16;s++){ l[s] = expf(l[s]-mx); sum += l[s]; }
        float r = 1.f/sum;
        #pragma unroll
        for (int s=0;s<16;s++) out[tid*16+s] = l[s]*r;
    }
    __syncthreads();
}
// C = BlockDiag(attn) @ Wv   (attn: [64][16] within-head)
__device__ __forceinline__ void bdv(float* Cm, const float* at, const float* Wv, int tid){
    int ty = tid>>4, tx = tid&15;
    float acc[4][4] = {};
    for (int s=0;s<16;s++){
        #pragma unroll
        for (int ii=0;ii<4;ii++){
            int row = ty*4+ii; int head = row >> 4;
            float a = at[row*16 + s];
            float4 wv = *(const float4*)&Wv[(head*16+s)*64 + tx*4];
            acc[ii][0] += a*wv.x; acc[ii][1] += a*wv.y;
            acc[ii][2] += a*wv.z; acc[ii][3] += a*wv.w;
        }
    }
    #pragma unroll
    for (int ii=0;ii<4;ii++)
        #pragma unroll
        for (int jj=0;jj<4;jj++)
            Cm[(ty*4+ii)*64 + tx*4+jj] = acc[ii][jj];
    __syncthreads();
}

__global__ void __launch_bounds__(256) smallmath_kernel(
    const float* __restrict__ Wq_c, const float* __restrict__ Wk_c, const float* __restrict__ Wv_c,
    const float* __restrict__ temp_c,
    const float* __restrict__ Wq_d, const float* __restrict__ Wk_d, const float* __restrict__ Wv_d,
    const float* __restrict__ temp_d,
    const float* __restrict__ proj1, const float* __restrict__ proj2)
{
    extern __shared__ float sm[];
    float* sA   = sm;             // 4096
    float* sB   = sA + 4096;
    float* sG   = sB + 4096;
    float* sT   = sG + 4096;
    float* sR   = sT + 4096;
    float* aA   = sR + 4096;      // 1024
    float* aB   = aA + 1024;      // 1024
    float* invq  = aB + 1024;     // 64
    float* invk1 = invq + 64;
    float* invk2 = invk1 + 64;

    int b = blockIdx.x;
    int tid = threadIdx.x;
    const float* GR = g_gram;
    #define GSLOT(s) (GR + ((size_t)(s)*BATCH + b)*4096)

    // ---------- common branch ----------
    ld_mat(sA, Wq_c, tid); ld_mat(sG, GSLOT(0), tid); __syncthreads();
    mm64_nn(sT, sA, sG, tid);
    rownorm_inv(invq, sT, sA, tid);
    ld_mat(sB, Wk_c, tid); ld_mat(sG, GSLOT(1), tid); __syncthreads();
    mm64_nn(sT, sB, sG, tid);
    rownorm_inv(invk1, sT, sB, tid);
    ld_mat(sG, GSLOT(2), tid); __syncthreads();
    mm64_nn(sT, sB, sG, tid);
    rownorm_inv(invk2, sT, sB, tid);
    ld_mat(sG, GSLOT(3), tid); __syncthreads();
    mm64_nn(sT, sA, sG, tid);
    mm64_nt(sR, sT, sB, tid);
    attn_softmax(aA, sR, invq, invk1, temp_c, tid);
    ld_mat(sG, GSLOT(4), tid); __syncthreads();
    mm64_nn(sT, sA, sG, tid);
    mm64_nt(sR, sT, sB, tid);
    attn_softmax(aB, sR, invq, invk2, temp_c, tid);
    if (tid < 64){
        #pragma unroll
        for (int s=0;s<16;s++) aA[tid*16+s] *= aB[tid*16+s];
    }
    __syncthreads();
    ld_mat(sB, Wv_c, tid); __syncthreads();
    bdv(sT, aA, sB, tid);
    ld_mat(sA, proj1, tid); __syncthreads();
    mm64_nn(sR, sA, sT, tid);
    for (int i=tid;i<4096;i+=256) g_M[((size_t)b*3+0)*4096 + i] = sR[i];
    __syncthreads();

    // ---------- differential branch ----------
    ld_mat(sA, Wq_d, tid); ld_mat(sG, GSLOT(5), tid); __syncthreads();
    mm64_nn(sT, sA, sG, tid);
    rownorm_inv(invq, sT, sA, tid);
    ld_mat(sB, Wk_d, tid); ld_mat(sG, GSLOT(1), tid); __syncthreads();
    mm64_nn(sT, sB, sG, tid);
    rownorm_inv(invk1, sT, sB, tid);
    ld_mat(sG, GSLOT(2), tid); __syncthreads();
    mm64_nn(sT, sB, sG, tid);
    rownorm_inv(invk2, sT, sB, tid);
    ld_mat(sG, GSLOT(6), tid); __syncthreads();
    mm64_nn(sT, sA, sG, tid);
    mm64_nt(sR, sT, sB, tid);
    attn_softmax(aA, sR, invq, invk1, temp_d, tid);
    ld_mat(sG, GSLOT(7), tid); __syncthreads();
    mm64_nn(sT, sA, sG, tid);
    mm64_nt(sR, sT, sB, tid);
    attn_softmax(aB, sR, invq, invk2, temp_d, tid);
    ld_mat(sB, Wv_d, tid); ld_mat(sA, proj2, tid); __syncthreads();
    bdv(sT, aA, sB, tid);
    mm64_nn(sR, sA, sT, tid);
    for (int i=tid;i<4096;i+=256) g_M[((size_t)b*3+1)*4096 + i] = sR[i];
    __syncthreads();
    bdv(sT, aB, sB, tid);
    mm64_nn(sR, sA, sT, tid);
    for (int i=tid;i<4096;i+=256) g_M[((size_t)b*3+2)*4096 + i] = sR[i];
    #undef GSLOT
}

// =====================================================================
// K4: common branch: Y = M_c @ (ni+ne) tile ; LN ; FFN ; residual ; store
// grid (1024, 4), block 256, 64 pixels/block
// =====================================================================
__global__ void __launch_bounds__(256) apply_common_kernel(
    const float* __restrict__ lnw, const float* __restrict__ lnb,
    const float* __restrict__ W1g, const float* __restrict__ b1g,
    const float* __restrict__ W2g, const float* __restrict__ b2g,
    float* __restrict__ outp)
{
    extern __shared__ float sm[];
    float* sM  = sm;                 // 64*68
    float* sX  = sM  + 64*68;        // 64*68 (reused as Z)
    float* sY  = sX  + 64*68;        // 64*68
    float* sH  = sY  + 64*68;        // 128*68
    float* sW1 = sH  + 128*68;       // 128*68
    float* sW2 = sW1 + 128*68;       // 64*132
    float* sb1 = sW2 + 64*132;       // 128
    float* sb2 = sb1 + 128;          // 64
    float* slw = sb2 + 64;           // 64
    float* slb = slw + 64;           // 64
    float* smu = slb + 64;           // 64
    float* srs = smu + 64;           // 64

    int b = blockIdx.y;
    int p0 = blockIdx.x * 64;
    int tid = threadIdx.x, ty = tid>>4, tx = tid&15;

    const float* Mg = g_M + ((size_t)b*3+0)*4096;
    for (int i=tid;i<4096;i+=256) sM[(i>>6)*68 + (i&63)] = Mg[i];
    for (int i=tid;i<8192;i+=256) sW1[(i>>6)*68 + (i&63)] = W1g[i];
    for (int i=tid;i<8192;i+=256) sW2[(i>>7)*132 + (i&127)] = W2g[i];
    if (tid < 128) sb1[tid] = b1g[tid];
    if (tid < 64){ sb2[tid]=b2g[tid]; slw[tid]=lnw[tid]; slb[tid]=lnb[tid]; }
    {
        int row = tid>>2, cb = (tid&3)*16;
        const float* pi = g_ni + ((size_t)(b*C64+row))*HW + p0 + cb;
        const float* pe = g_ne + ((size_t)(b*C64+row))*HW + p0 + cb;
        #pragma unroll
        for (int j=0;j<16;j+=4){
            float4 a = *(const float4*)&pi[j];
            float4 e = *(const float4*)&pe[j];
            sX[row*68+cb+j+0]=a.x+e.x; sX[row*68+cb+j+1]=a.y+e.y;
            sX[row*68+cb+j+2]=a.z+e.z; sX[row*68+cb+j+3]=a.w+e.w;
        }
    }
    __syncthreads();
    // GEMM1: Y = M @ X
    {
        float acc[4][4] = {};
        for (int k=0;k<64;k++){
            float4 xv = *(const float4*)&sX[k*68 + tx*4];
            float x4[4] = {xv.x,xv.y,xv.z,xv.w};
            #pragma unroll
            for (int ii=0;ii<4;ii++){
                float m = sM[(ty*4+ii)*68 + k];
                #pragma unroll
                for (int jj=0;jj<4;jj++) acc[ii][jj] += m*x4[jj];
            }
        }
        #pragma unroll
        for (int ii=0;ii<4;ii++)
            #pragma unroll
            for (int jj=0;jj<4;jj++)
                sY[(ty*4+ii)*68 + tx*4+jj] = acc[ii][jj];
    }
    __syncthreads();
    // LN stats per pixel
    if (tid < 64){
        float s=0.f, ss=0.f;
        for (int c=0;c<64;c++){ float v = sY[c*68+tid]; s += v; ss += v*v; }
        float mu = s*(1.f/64.f);
        float var = ss*(1.f/64.f) - mu*mu;
        smu[tid] = mu; srs[tid] = rsqrtf(var + EPSF);
    }
    __syncthreads();
    // Z (into sX)
    for (int i=tid;i<4096;i+=256){
        int c = i>>6, px = i&63;
        sX[c*68+px] = (sY[c*68+px]-smu[px])*srs[px]*slw[c] + slb[c];
    }
    __syncthreads();
    // GEMM2: H = gelu(W1 @ Z + b1)
    {
        float acc[8][4] = {};
        for (int k=0;k<64;k++){
            float4 zv = *(const float4*)&sX[k*68 + tx*4];
            float z4[4] = {zv.x,zv.y,zv.z,zv.w};
            #pragma unroll
            for (int rr=0;rr<8;rr++){
                float w = sW1[(ty*8+rr)*68 + k];
                #pragma unroll
                for (int jj=0;jj<4;jj++) acc[rr][jj] += w*z4[jj];
            }
        }
        #pragma unroll
        for (int rr=0;rr<8;rr++)
            #pragma unroll
            for (int jj=0;jj<4;jj++){
                float h = acc[rr][jj] + sb1[ty*8+rr];
                sH[(ty*8+rr)*68 + tx*4+jj] = 0.5f*h*(1.f + erff(h*0.70710678118654752f));
            }
    }
    __syncthreads();
    // GEMM3 + bias + residual + store
    {
        float acc[4][4] = {};
        for (int k=0;k<128;k++){
            float4 hv = *(const float4*)&sH[k*68 + tx*4];
            float h4[4] = {hv.x,hv.y,hv.z,hv.w};
            #pragma unroll
            for (int ii=0;ii<4;ii++){
                float w = sW2[(ty*4+ii)*132 + k];
                #pragma unroll
                for (int jj=0;jj<4;jj++) acc[ii][jj] += w*h4[jj];
            }
        }
        #pragma unroll
        for (int ii=0;ii<4;ii++){
            int row = ty*4+ii;
            float4 o;
            o.x = acc[ii][0] + sb2[row] + sY[row*68 + tx*4+0];
            o.y = acc[ii][1] + sb2[row] + sY[row*68 + tx*4+1];
            o.z = acc[ii][2] + sb2[row] + sY[row*68 + tx*4+2];
            o.w = acc[ii][3] + sb2[row] + sY[row*68 + tx*4+3];
            *(float4*)&outp[((size_t)(b*C64+row))*HW + p0 + tx*4] = o;
        }
    }
}

// =====================================================================
// K5: diff branch: Y = M_id @ ni + M_ed @ ne ; LN ; FFN ; residual
// =====================================================================
__global__ void __launch_bounds__(256) apply_diff_kernel(
    const float* __restrict__ lnw, const float* __restrict__ lnb,
    const float* __restrict__ W1g, const float* __restrict__ b1g,
    const float* __restrict__ W2g, const float* __restrict__ b2g,
    float* __restrict__ outp)
{
    extern __shared__ float sm[];
    float* sM  = sm;                 // 64*132 (M_id | M_ed)
    float* sX  = sM  + 64*132;       // 128*68 (ni;ne), rows 0..63 reused as Z
    float* sY  = sX  + 128*68;       // 64*68
    float* sH  = sY  + 64*68;        // 128*68
    float* sW1 = sH  + 128*68;       // 128*68
    float* sW2 = sW1 + 128*68;       // 64*132
    float* sb1 = sW2 + 64*132;       // 128
    float* sb2 = sb1 + 128;
    float* slw = sb2 + 64;
    float* slb = slw + 64;
    float* smu = slb + 64;
    float* srs = smu + 64;

    int b = blockIdx.y;
    int p0 = blockIdx.x * 64;
    int tid = threadIdx.x, ty = tid>>4, tx = tid&15;

    const float* Mi = g_M + ((size_t)b*3+1)*4096;
    const float* Me = g_M + ((size_t)b*3+2)*4096;
    for (int i=tid;i<4096;i+=256){
        int r = i>>6, k = i&63;
        sM[r*132 + k]      = Mi[i];
        sM[r*132 + 64 + k] = Me[i];
    }
    for (int i=tid;i<8192;i+=256) sW1[(i>>6)*68 + (i&63)] = W1g[i];
    for (int i=tid;i<8192;i+=256) sW2[(i>>7)*132 + (i&127)] = W2g[i];
    if (tid < 128) sb1[tid] = b1g[tid];
    if (tid < 64){ sb2[tid]=b2g[tid]; slw[tid]=lnw[tid]; slb[tid]=lnb[tid]; }
    for (int i=tid;i<8192;i+=256){
        int r = i>>6, px = i&63;
        float v = (r < 64) ? g_ni[((size_t)(b*C64+r))*HW + p0 + px]
                           : g_ne[((size_t)(b*C64+(r-64)))*HW + p0 + px];
        sX[r*68 + px] = v;
    }
    __syncthreads();
    // GEMM1: Y = [M_id|M_ed] @ [ni;ne]
    {
        float acc[4][4] = {};
        for (int k=0;k<128;k++){
            float4 xv = *(const float4*)&sX[k*68 + tx*4];
            float x4[4] = {xv.x,xv.y,xv.z,xv.w};
            #pragma unroll
            for (int ii=0;ii<4;ii++){
                float m = sM[(ty*4+ii)*132 + k];
                #pragma unroll
                for (int jj=0;jj<4;jj++) acc[ii][jj] += m*x4[jj];
            }
        }
        #pragma unroll
        for (int ii=0;ii<4;ii++)
            #pragma unroll
            for (int jj=0;jj<4;jj++)
                sY[(ty*4+ii)*68 + tx*4+jj] = acc[ii][jj];
    }
    __syncthreads();
    if (tid < 64){
        float s=0.f, ss=0.f;
        for (int c=0;c<64;c++){ float v = sY[c*68+tid]; s += v; ss += v*v; }
        float mu = s*(1.f/64.f);
        float var = ss*(1.f/64.f) - mu*mu;
        smu[tid] = mu; srs[tid] = rsqrtf(var + EPSF);
    }
    __syncthreads();
    for (int i=tid;i<4096;i+=256){
        int c = i>>6, px = i&63;
        sX[c*68+px] = (sY[c*68+px]-smu[px])*srs[px]*slw[c] + slb[c];
    }
    __syncthreads();
    {
        float acc[8][4] = {};
        for (int k=0;k<64;k++){
            float4 zv = *(const float4*)&sX[k*68 + tx*4];
            float z4[4] = {zv.x,zv.y,zv.z,zv.w};
            #pragma unroll
            for (int rr=0;rr<8;rr++){
                float w = sW1[(ty*8+rr)*68 + k];
                #pragma unroll
                for (int jj=0;jj<4;jj++) acc[rr][jj] += w*z4[jj];
            }
        }
        #pragma unroll
        for (int rr=0;rr<8;rr++)
            #pragma unroll
            for (int jj=0;jj<4;jj++){
                float h = acc[rr][jj] + sb1[ty*8+rr];
                sH[(ty*8+rr)*68 + tx*4+jj] = 0.5f*h*(1.f + erff(h*0.70710678118654752f));
            }
    }
    __syncthreads();
    {
        float acc[4][4] = {};
        for (int k=0;k<128;k++){
            float4 hv = *(const float4*)&sH[k*68 + tx*4];
            float h4[4] = {hv.x,hv.y,hv.z,hv.w};
            #pragma unroll
            for (int ii=0;ii<4;ii++){
                float w = sW2[(ty*4+ii)*132 + k];
                #pragma unroll
                for (int jj=0;jj<4;jj++) acc[ii][jj] += w*h4[jj];
            }
        }
        #pragma unroll
        for (int ii=0;ii<4;ii++){
            int row = ty*4+ii;
            float4 o;
            o.x = acc[ii][0] + sb2[row] + sY[row*68 + tx*4+0];
            o.y = acc[ii][1] + sb2[row] + sY[row*68 + tx*4+1];
            o.z = acc[ii][2] + sb2[row] + sY[row*68 + tx*4+2];
            o.w = acc[ii][3] + sb2[row] + sY[row*68 + tx*4+3];
            *(float4*)&outp[((size_t)(b*C64+row))*HW + p0 + tx*4] = o;
        }
    }
}

// =====================================================================
extern "C" void kernel_launch(void* const* d_in, const int* in_sizes, int n_in,
                              void* d_out, int out_size)
{
    (void)in_sizes; (void)n_in; (void)out_size;
    const float* image  = (const float*)d_in[0];
    const float* event_ = (const float*)d_in[1];
    const float* Wq_c = (const float*)d_in[2];
    const float* Wk_c = (const float*)d_in[3];
    const float* Wv_c = (const float*)d_in[4];
    const float* temp_c = (const float*)d_in[5];
    const float* Wq_d = (const float*)d_in[6];
    const float* Wk_d = (const float*)d_in[7];
    const float* Wv_d = (const float*)d_in[8];
    const float* temp_d = (const float*)d_in[9];
    const float* ln_img_w = (const float*)d_in[10];
    const float* ln_img_b = (const float*)d_in[11];
    const float* ln_evt_w = (const float*)d_in[12];
    const float* ln_evt_b = (const float*)d_in[13];
    const float* ln_com_w = (const float*)d_in[14];
    const float* ln_com_b = (const float*)d_in[15];
    const float* ln_dif_w = (const float*)d_in[16];
    const float* ln_dif_b = (const float*)d_in[17];
    const float* ln1_w = (const float*)d_in[18];
    const float* ln1_b = (const float*)d_in[19];
    const float* ln2_w = (const float*)d_in[20];
    const float* ln2_b = (const float*)d_in[21];
    const float* fc1c_w = (const float*)d_in[22];
    const float* fc1c_b = (const float*)d_in[23];
    const float* fc2c_w = (const float*)d_in[24];
    const float* fc2c_b = (const float*)d_in[25];
    const float* fc1d_w = (const float*)d_in[26];
    const float* fc1d_b = (const float*)d_in[27];
    const float* fc2d_w = (const float*)d_in[28];
    const float* fc2d_b = (const float*)d_in[29];
    const float* proj1_w = (const float*)d_in[30];
    const float* proj2_w = (const float*)d_in[31];

    float* outc = (float*)d_out;
    float* outd = outc + (size_t)BATCH*C64*HW;

    const int SM3 = (4096*5 + 1024*2 + 64*3) * sizeof(float);
    const int SM4 = (64*68*3 + 128*68*2 + 64*132 + 128 + 64*5) * sizeof(float);
    const int SM5 = (64*132 + 128*68 + 64*68 + 128*68*2 + 64*132 + 128 + 64*5) * sizeof(float);

    cudaFuncSetAttribute(smallmath_kernel,    cudaFuncAttributeMaxDynamicSharedMemorySize, SM3);
    cudaFuncSetAttribute(apply_common_kernel, cudaFuncAttributeMaxDynamicSharedMemorySize, SM4);
    cudaFuncSetAttribute(apply_diff_kernel,   cudaFuncAttributeMaxDynamicSharedMemorySize, SM5);

    ln_kernel<<<BATCH*(HW/256), 256>>>(image, event_,
        ln_img_w, ln_img_b, ln_evt_w, ln_evt_b,
        ln_com_w, ln_com_b, ln_dif_w, ln_dif_b);

    dim3 g2(32, 8, BATCH);
    gram_kernel<<<g2, 256>>>();

    smallmath_kernel<<<BATCH, 256, SM3>>>(Wq_c, Wk_c, Wv_c, temp_c,
                                          Wq_d, Wk_d, Wv_d, temp_d,
                                          proj1_w, proj2_w);

    dim3 g4(HW/64, BATCH);
    apply_common_kernel<<<g4, 256, SM4>>>(ln1_w, ln1_b, fc1c_w, fc1c_b,
                                          fc2c_w, fc2c_b, outc);
    apply_diff_kernel<<<g4, 256, SM5>>>(ln2_w, ln2_b, fc1d_w, fc1d_b,
                                        fc2d_w, fc2d_b, outd);
}

// round 6
// speedup vs baseline: 1.1338x; 1.1338x over previous
#include <cuda_runtime.h>
#include <cuda_bf16.h>
#include <math.h>
#include <stdint.h>

#define BATCH 4
#define C64   64
#define HW    65536
#define HEADS 4
#define HID   128
#define EPSF  1e-5f

#define TOT (BATCH*C64*HW)

// ---------------- scratch (device globals; no allocs) ----------------
__device__ float g_ni[TOT];
__device__ float g_ne[TOT];
__device__ float g_nc[TOT];
__device__ float g_nd[TOT];
// stacked gram: per batch 256x256 over rows [ni(0-63);ne;nc;nd]
__device__ float g_gram256[BATCH*256*256];
// per batch: 0=M_c, 1=M_id, 2=M_ed
__device__ float g_M[BATCH*3*C64*C64];

// ======================= helpers ========================
__device__ __forceinline__ uint32_t smem_u32(const void* p){
    uint32_t a;
    asm("{ .reg .u64 t; cvta.to.shared.u64 t, %1; cvt.u32.u64 %0, t; }" : "=r"(a) : "l"(p));
    return a;
}
__device__ __forceinline__ void ldm_x4(uint32_t* r, uint32_t addr){
    asm volatile("ldmatrix.sync.aligned.m8n8.x4.shared.b16 {%0,%1,%2,%3}, [%4];"
        : "=r"(r[0]), "=r"(r[1]), "=r"(r[2]), "=r"(r[3]) : "r"(addr));
}
__device__ __forceinline__ void mma_bf16(float& d0, float& d1, float& d2, float& d3,
        uint32_t a0, uint32_t a1, uint32_t a2, uint32_t a3,
        uint32_t b0, uint32_t b1){
    asm volatile("mma.sync.aligned.m16n8k16.row.col.f32.bf16.bf16.f32 "
        "{%0,%1,%2,%3}, {%4,%5,%6,%7}, {%8,%9}, {%0,%1,%2,%3};"
        : "+f"(d0), "+f"(d1), "+f"(d2), "+f"(d3)
        : "r"(a0), "r"(a1), "r"(a2), "r"(a3), "r"(b0), "r"(b1));
}

// =====================================================================
// K1: channel LayerNorm for ni/ne/nc/nd  (+ zero gram accumulator)
// grid: BATCH*(HW/256), block 256 (1 thread = 1 pixel)
// =====================================================================
__global__ void __launch_bounds__(256) ln_kernel(
    const float* __restrict__ img, const float* __restrict__ evt,
    const float* __restrict__ wi, const float* __restrict__ bi,
    const float* __restrict__ we, const float* __restrict__ be,
    const float* __restrict__ wc, const float* __restrict__ bc,
    const float* __restrict__ wd, const float* __restrict__ bd)
{
    // zero gram accumulator (BATCH*256*256 = 262144 floats) with first 256 blocks
    if (blockIdx.x < 256) {
        int base = blockIdx.x * 1024 + threadIdx.x * 4;
        g_gram256[base+0] = 0.f; g_gram256[base+1] = 0.f;
        g_gram256[base+2] = 0.f; g_gram256[base+3] = 0.f;
    }
    int b  = blockIdx.x >> 8;
    int p  = ((blockIdx.x & 255) << 8) + threadIdx.x;
    const float* ip = img + (size_t)b*C64*HW + p;
    const float* ep = evt + (size_t)b*C64*HW + p;

    float si=0.f, se=0.f, sii=0.f, see=0.f, sie=0.f;
    #pragma unroll 8
    for (int c=0;c<C64;c++){
        float iv = ip[c*HW], ev = ep[c*HW];
        si += iv; se += ev; sii += iv*iv; see += ev*ev; sie += iv*ev;
    }
    const float inv64 = 1.f/64.f;
    float mi = si*inv64, me = se*inv64;
    float vi = sii*inv64 - mi*mi;
    float ve = see*inv64 - me*me;
    float mc = (si+se)*inv64, md = (si-se)*inv64;
    float vc = (sii + 2.f*sie + see)*inv64 - mc*mc;
    float vd = (sii - 2.f*sie + see)*inv64 - md*md;
    float ri = rsqrtf(vi+EPSF), re = rsqrtf(ve+EPSF);
    float rc = rsqrtf(vc+EPSF), rd = rsqrtf(vd+EPSF);

    size_t ob = (size_t)b*C64*HW + p;
    #pragma unroll 8
    for (int c=0;c<C64;c++){
        float iv = ip[c*HW], ev = ep[c*HW];
        g_ni[ob + (size_t)c*HW] = (iv-mi)*ri*wi[c] + bi[c];
        g_ne[ob + (size_t)c*HW] = (ev-me)*re*we[c] + be[c];
        g_nc[ob + (size_t)c*HW] = (iv+ev-mc)*rc*wc[c] + bc[c];
        g_nd[ob + (size_t)c*HW] = (iv-ev-md)*rd*wd[c] + bd[c];
    }
}

// =====================================================================
// K2: stacked Gram via mma.sync bf16 hi/lo (3 passes), fp32 accum.
// S = [ni;ne;nc;nd] (256 x HW per batch); G = S S^T (256x256).
// grid (32 ksplit, 4 output tiles 2x2, 4 batches), block 256 (8 warps).
// CTA tile 128x128 of G; warp tile 32x64 (warps 4x2); K chunk 32.
// =====================================================================
#define GK_KSPLIT 32
#define GK_KRANGE (HW/GK_KSPLIT)   // 2048
#define GK_KC     32
#define GK_NCH    (GK_KRANGE/GK_KC) // 64
#define SPITCH    40                 // bf16 elems per smem row (80B, conflict-free)

__global__ void __launch_bounds__(256) gram_mma_kernel()
{
    __shared__ __align__(16) unsigned short sAhi[128*SPITCH];
    __shared__ __align__(16) unsigned short sAlo[128*SPITCH];
    __shared__ __align__(16) unsigned short sBhi[128*SPITCH];
    __shared__ __align__(16) unsigned short sBlo[128*SPITCH];

    int tid = threadIdx.x;
    int wid = tid >> 5, lane = tid & 31;
    int ks = blockIdx.x, tileid = blockIdx.y, b = blockIdx.z;
    int m0 = (tileid >> 1) * 128;
    int n0 = (tileid & 1) * 128;
    int warp_m = (wid >> 1) * 32;     // 0,32,64,96
    int warp_n = (wid & 1) * 64;      // 0,64

    const float* tens[4] = {g_ni, g_ne, g_nc, g_nd};

    // loader mapping: thread -> row tid>>1 (0..127), col half (tid&1)*16
    int lr = tid >> 1;
    int lc = (tid & 1) * 16;
    const float* srcA = tens[(m0+lr)>>6] + ((size_t)(b*C64) + ((m0+lr)&63))*HW + (size_t)ks*GK_KRANGE + lc;
    const float* srcB = tens[(n0+lr)>>6] + ((size_t)(b*C64) + ((n0+lr)&63))*HW + (size_t)ks*GK_KRANGE + lc;

    uint32_t aHi = smem_u32(sAhi), aLo = smem_u32(sAlo);
    uint32_t bHi = smem_u32(sBhi), bLo = smem_u32(sBlo);

    // ldmatrix offsets (bytes)
    int rowA = warp_m + (lane & 15);
    int colA = (lane >> 4) * 8;
    uint32_t offA = (uint32_t)(rowA*SPITCH + colA) * 2;
    int rowB = warp_n + (lane & 7) + ((lane >> 4) & 1) * 8;
    int colB = ((lane >> 3) & 1) * 8;
    uint32_t offB = (uint32_t)(rowB*SPITCH + colB) * 2;

    float acc[2][8][4];
    #pragma unroll
    for (int i=0;i<2;i++)
        #pragma unroll
        for (int j=0;j<8;j++)
            #pragma unroll
            for (int k=0;k<4;k++) acc[i][j][k] = 0.f;

    for (int t = 0; t < GK_NCH; t++) {
        __syncthreads();
        int kc = t * GK_KC;
        // load + convert A rows and B rows (hi/lo bf16)
        {
            const float* pa = srcA + kc;
            const float* pb = srcB + kc;
            unsigned short* dAh = sAhi + lr*SPITCH + lc;
            unsigned short* dAl = sAlo + lr*SPITCH + lc;
            unsigned short* dBh = sBhi + lr*SPITCH + lc;
            unsigned short* dBl = sBlo + lr*SPITCH + lc;
            #pragma unroll
            for (int j=0;j<16;j+=4){
                float4 v = *(const float4*)&pa[j];
                __nv_bfloat16 h0=__float2bfloat16(v.x), h1=__float2bfloat16(v.y);
                __nv_bfloat16 h2=__float2bfloat16(v.z), h3=__float2bfloat16(v.w);
                __nv_bfloat16 l0=__float2bfloat16(v.x-__bfloat162float(h0));
                __nv_bfloat16 l1=__float2bfloat16(v.y-__bfloat162float(h1));
                __nv_bfloat16 l2=__float2bfloat16(v.z-__bfloat162float(h2));
                __nv_bfloat16 l3=__float2bfloat16(v.w-__bfloat162float(h3));
                uint2 hh, ll;
                hh.x = (uint32_t)__bfloat16_as_ushort(h0) | ((uint32_t)__bfloat16_as_ushort(h1)<<16);
                hh.y = (uint32_t)__bfloat16_as_ushort(h2) | ((uint32_t)__bfloat16_as_ushort(h3)<<16);
                ll.x = (uint32_t)__bfloat16_as_ushort(l0) | ((uint32_t)__bfloat16_as_ushort(l1)<<16);
                ll.y = (uint32_t)__bfloat16_as_ushort(l2) | ((uint32_t)__bfloat16_as_ushort(l3)<<16);
                *(uint2*)&dAh[j] = hh;
                *(uint2*)&dAl[j] = ll;
                float4 w = *(const float4*)&pb[j];
                __nv_bfloat16 g0=__float2bfloat16(w.x), g1=__float2bfloat16(w.y);
                __nv_bfloat16 g2=__float2bfloat16(w.z), g3=__float2bfloat16(w.w);
                __nv_bfloat16 m0b=__float2bfloat16(w.x-__bfloat162float(g0));
                __nv_bfloat16 m1b=__float2bfloat16(w.y-__bfloat162float(g1));
                __nv_bfloat16 m2b=__float2bfloat16(w.z-__bfloat162float(g2));
                __nv_bfloat16 m3b=__float2bfloat16(w.w-__bfloat162float(g3));
                uint2 gh, gl;
                gh.x = (uint32_t)__bfloat16_as_ushort(g0) | ((uint32_t)__bfloat16_as_ushort(g1)<<16);
                gh.y = (uint32_t)__bfloat16_as_ushort(g2) | ((uint32_t)__bfloat16_as_ushort(g3)<<16);
                gl.x = (uint32_t)__bfloat16_as_ushort(m0b) | ((uint32_t)__bfloat16_as_ushort(m1b)<<16);
                gl.y = (uint32_t)__bfloat16_as_ushort(m2b) | ((uint32_t)__bfloat16_as_ushort(m3b)<<16);
                *(uint2*)&dBh[j] = gh;
                *(uint2*)&dBl[j] = gl;
            }
        }
        __syncthreads();
        #pragma unroll
        for (int k16 = 0; k16 < GK_KC; k16 += 16) {
            uint32_t kb = (uint32_t)(k16 * 2);
            uint32_t Ah0[4], Ah1[4], Al0[4], Al1[4];
            ldm_x4(Ah0, aHi + offA + kb);
            ldm_x4(Ah1, aHi + offA + kb + 16*SPITCH*2);
            ldm_x4(Al0, aLo + offA + kb);
            ldm_x4(Al1, aLo + offA + kb + 16*SPITCH*2);
            #pragma unroll
            for (int np = 0; np < 4; np++) {
                uint32_t Bh[4], Bl[4];
                uint32_t ob = offB + kb + (uint32_t)(np*16*SPITCH*2);
                ldm_x4(Bh, bHi + ob);
                ldm_x4(Bl, bLo + ob);
                int n2 = np*2;
                // hi*hi
                mma_bf16(acc[0][n2][0],acc[0][n2][1],acc[0][n2][2],acc[0][n2][3],
                         Ah0[0],Ah0[1],Ah0[2],Ah0[3], Bh[0],Bh[1]);
                mma_bf16(acc[0][n2+1][0],acc[0][n2+1][1],acc[0][n2+1][2],acc[0][n2+1][3],
                         Ah0[0],Ah0[1],Ah0[2],Ah0[3], Bh[2],Bh[3]);
                mma_bf16(acc[1][n2][0],acc[1][n2][1],acc[1][n2][2],acc[1][n2][3],
                         Ah1[0],Ah1[1],Ah1[2],Ah1[3], Bh[0],Bh[1]);
                mma_bf16(acc[1][n2+1][0],acc[1][n2+1][1],acc[1][n2+1][2],acc[1][n2+1][3],
                         Ah1[0],Ah1[1],Ah1[2],Ah1[3], Bh[2],Bh[3]);
                // hi*lo
                mma_bf16(acc[0][n2][0],acc[0][n2][1],acc[0][n2][2],acc[0][n2][3],
                         Ah0[0],Ah0[1],Ah0[2],Ah0[3], Bl[0],Bl[1]);
                mma_bf16(acc[0][n2+1][0],acc[0][n2+1][1],acc[0][n2+1][2],acc[0][n2+1][3],
                         Ah0[0],Ah0[1],Ah0[2],Ah0[3], Bl[2],Bl[3]);
                mma_bf16(acc[1][n2][0],acc[1][n2][1],acc[1][n2][2],acc[1][n2][3],
                         Ah1[0],Ah1[1],Ah1[2],Ah1[3], Bl[0],Bl[1]);
                mma_bf16(acc[1][n2+1][0],acc[1][n2+1][1],acc[1][n2+1][2],acc[1][n2+1][3],
                         Ah1[0],Ah1[1],Ah1[2],Ah1[3], Bl[2],Bl[3]);
                // lo*hi
                mma_bf16(acc[0][n2][0],acc[0][n2][1],acc[0][n2][2],acc[0][n2][3],
                         Al0[0],Al0[1],Al0[2],Al0[3], Bh[0],Bh[1]);
                mma_bf16(acc[0][n2+1][0],acc[0][n2+1][1],acc[0][n2+1][2],acc[0][n2+1][3],
                         Al0[0],Al0[1],Al0[2],Al0[3], Bh[2],Bh[3]);
                mma_bf16(acc[1][n2][0],acc[1][n2][1],acc[1][n2][2],acc[1][n2][3],
                         Al1[0],Al1[1],Al1[2],Al1[3], Bh[0],Bh[1]);
                mma_bf16(acc[1][n2+1][0],acc[1][n2+1][1],acc[1][n2+1][2],acc[1][n2+1][3],
                         Al1[0],Al1[1],Al1[2],Al1[3], Bh[2],Bh[3]);
            }
        }
    }

    // epilogue: atomicAdd into g_gram256
    float* G = g_gram256 + (size_t)b*65536;
    int rbase = m0 + warp_m + (lane >> 2);
    int cbase = n0 + warp_n + (lane & 3)*2;
    #pragma unroll
    for (int i=0;i<2;i++){
        #pragma unroll
        for (int ns=0;ns<8;ns++){
            int rr = rbase + i*16;
            int cc = cbase + ns*8;
            atomicAdd(&G[rr*256 + cc],       acc[i][ns][0]);
            atomicAdd(&G[rr*256 + cc + 1],   acc[i][ns][1]);
            atomicAdd(&G[(rr+8)*256 + cc],   acc[i][ns][2]);
            atomicAdd(&G[(rr+8)*256 + cc+1], acc[i][ns][3]);
        }
    }
}

// =====================================================================
// K3: tiny per-batch math -> M_c, M_id, M_ed. grid 4, block 256.
// =====================================================================
__device__ __forceinline__ void ld_mat(float* s, const float* __restrict__ g, int tid){
    for (int i=tid; i<4096; i+=256) s[i] = g[i];
}
// load 64x64 block from the stacked 256x256 gram (row stride 256)
__device__ __forceinline__ void ld_matg(float* s, const float* __restrict__ g, int tid){
    for (int i=tid; i<4096; i+=256) s[i] = g[(i>>6)*256 + (i&63)];
}
__device__ __forceinline__ void mm64_nn(float* Cm, const float* A, const float* Bm, int tid){
    int ty = tid>>4, tx = tid&15;
    float acc[4][4] = {};
    for (int k=0;k<64;k++){
        float4 bv = *(const float4*)&Bm[k*64 + tx*4];
        float b4[4] = {bv.x,bv.y,bv.z,bv.w};
        #pragma unroll
        for (int ii=0;ii<4;ii++){
            float a = A[(ty*4+ii)*64 + k];
            #pragma unroll
            for (int jj=0;jj<4;jj++) acc[ii][jj] += a*b4[jj];
        }
    }
    #pragma unroll
    for (int ii=0;ii<4;ii++)
        #pragma unroll
        for (int jj=0;jj<4;jj++)
            Cm[(ty*4+ii)*64 + tx*4+jj] = acc[ii][jj];
    __syncthreads();
}
__device__ __forceinline__ void mm64_nt(float* Cm, const float* A, const float* Bm, int tid){
    int ty = tid>>4, tx = tid&15;
    float acc[4][4] = {};
    for (int k=0;k<64;k++){
        float a4[4], b4[4];
        #pragma unroll
        for (int ii=0;ii<4;ii++) a4[ii] = A[(ty*4+ii)*64 + k];
        #pragma unroll
        for (int jj=0;jj<4;jj++) b4[jj] = Bm[(tx*4+jj)*64 + k];
        #pragma unroll
        for (int ii=0;ii<4;ii++)
            #pragma unroll
            for (int jj=0;jj<4;jj++) acc[ii][jj] += a4[ii]*b4[jj];
    }
    #pragma unroll
    for (int ii=0;ii<4;ii++)
        #pragma unroll
        for (int jj=0;jj<4;jj++)
            Cm[(ty*4+ii)*64 + tx*4+jj] = acc[ii][jj];
    __syncthreads();
}
__device__ __forceinline__ void rownorm_inv(float* inv, const float* T, const float* Wm, int tid){
    if (tid < 64){
        float s = 0.f;
        for (int k=0;k<64;k++) s += T[tid*64+k]*Wm[tid*64+k];
        inv[tid] = 1.f / fmaxf(sqrtf(fmaxf(s, 0.f)), 1e-12f);
    }
    __syncthreads();
}
__device__ __forceinline__ void attn_softmax(float* out, const float* raw,
        const float* invq, const float* invk, const float* __restrict__ temp, int tid){
    if (tid < 64){
        int head = tid >> 4, base = head*16;
        float t = temp[head];
        float l[16]; float mx = -1e30f;
        #pragma unroll
        for (int s=0;s<16;s++){
            l[s] = raw[tid*64 + base + s] * invq[tid] * invk[base+s] * t;
            mx = fmaxf(mx, l[s]);
        }
        float sum = 0.f;
        #pragma unroll
        for (int s=0;s<16;s++){ l[s] = expf(l[s]-mx); sum += l[s]; }
        float r = 1.f/sum;
        #pragma unroll
        for (int s=0;s<16;s++) out[tid*16+s] = l[s]*r;
    }
    __syncthreads();
}
__device__ __forceinline__ void bdv(float* Cm, const float* at, const float* Wv, int tid){
    int ty = tid>>4, tx = tid&15;
    float acc[4][4] = {};
    for (int s=0;s<16;s++){
        #pragma unroll
        for (int ii=0;ii<4;ii++){
            int row = ty*4+ii; int head = row >> 4;
            float a = at[row*16 + s];
            float4 wv = *(const float4*)&Wv[(head*16+s)*64 + tx*4];
            acc[ii][0] += a*wv.x; acc[ii][1] += a*wv.y;
            acc[ii][2] += a*wv.z; acc[ii][3] += a*wv.w;
        }
    }
    #pragma unroll
    for (int ii=0;ii<4;ii++)
        #pragma unroll
        for (int jj=0;jj<4;jj++)
            Cm[(ty*4+ii)*64 + tx*4+jj] = acc[ii][jj];
    __syncthreads();
}

__global__ void __launch_bounds__(256) smallmath_kernel(
    const float* __restrict__ Wq_c, const float* __restrict__ Wk_c, const float* __restrict__ Wv_c,
    const float* __restrict__ temp_c,
    const float* __restrict__ Wq_d, const float* __restrict__ Wk_d, const float* __restrict__ Wv_d,
    const float* __restrict__ temp_d,
    const float* __restrict__ proj1, const float* __restrict__ proj2)
{
    extern __shared__ float sm[];
    float* sA   = sm;             // 4096
    float* sB   = sA + 4096;
    float* sG   = sB + 4096;
    float* sT   = sG + 4096;
    float* sR   = sT + 4096;
    float* aA   = sR + 4096;      // 1024
    float* aB   = aA + 1024;      // 1024
    float* invq  = aB + 1024;     // 64
    float* invk1 = invq + 64;
    float* invk2 = invk1 + 64;

    int b = blockIdx.x;
    int tid = threadIdx.x;
    // stacked gram blocks: row/col tensor ids: 0=ni 1=ne 2=nc 3=nd
    #define GB(bi,bj) (g_gram256 + (size_t)b*65536 + (bi)*64*256 + (bj)*64)

    // ---------- common branch ----------
    ld_mat(sA, Wq_c, tid); ld_matg(sG, GB(2,2), tid); __syncthreads();
    mm64_nn(sT, sA, sG, tid);
    rownorm_inv(invq, sT, sA, tid);
    ld_mat(sB, Wk_c, tid); ld_matg(sG, GB(0,0), tid); __syncthreads();
    mm64_nn(sT, sB, sG, tid);
    rownorm_inv(invk1, sT, sB, tid);
    ld_matg(sG, GB(1,1), tid); __syncthreads();
    mm64_nn(sT, sB, sG, tid);
    rownorm_inv(invk2, sT, sB, tid);
    ld_matg(sG, GB(2,0), tid); __syncthreads();
    mm64_nn(sT, sA, sG, tid);
    mm64_nt(sR, sT, sB, tid);
    attn_softmax(aA, sR, invq, invk1, temp_c, tid);
    ld_matg(sG, GB(2,1), tid); __syncthreads();
    mm64_nn(sT, sA, sG, tid);
    mm64_nt(sR, sT, sB, tid);
    attn_softmax(aB, sR, invq, invk2, temp_c, tid);
    if (tid < 64){
        #pragma unroll
        for (int s=0;s<16;s++) aA[tid*16+s] *= aB[tid*16+s];
    }
    __syncthreads();
    ld_mat(sB, Wv_c, tid); __syncthreads();
    bdv(sT, aA, sB, tid);
    ld_mat(sA, proj1, tid); __syncthreads();
    mm64_nn(sR, sA, sT, tid);
    for (int i=tid;i<4096;i+=256) g_M[((size_t)b*3+0)*4096 + i] = sR[i];
    __syncthreads();

    // ---------- differential branch ----------
    ld_mat(sA, Wq_d, tid); ld_matg(sG, GB(3,3), tid); __syncthreads();
    mm64_nn(sT, sA, sG, tid);
    rownorm_inv(invq, sT, sA, tid);
    ld_mat(sB, Wk_d, tid); ld_matg(sG, GB(0,0), tid); __syncthreads();
    mm64_nn(sT, sB, sG, tid);
    rownorm_inv(invk1, sT, sB, tid);
    ld_matg(sG, GB(1,1), tid); __syncthreads();
    mm64_nn(sT, sB, sG, tid);
    rownorm_inv(invk2, sT, sB, tid);
    ld_matg(sG, GB(3,0), tid); __syncthreads();
    mm64_nn(sT, sA, sG, tid);
    mm64_nt(sR, sT, sB, tid);
    attn_softmax(aA, sR, invq, invk1, temp_d, tid);
    ld_matg(sG, GB(3,1), tid); __syncthreads();
    mm64_nn(sT, sA, sG, tid);
    mm64_nt(sR, sT, sB, tid);
    attn_softmax(aB, sR, invq, invk2, temp_d, tid);
    ld_mat(sB, Wv_d, tid); ld_mat(sA, proj2, tid); __syncthreads();
    bdv(sT, aA, sB, tid);
    mm64_nn(sR, sA, sT, tid);
    for (int i=tid;i<4096;i+=256) g_M[((size_t)b*3+1)*4096 + i] = sR[i];
    __syncthreads();
    bdv(sT, aB, sB, tid);
    mm64_nn(sR, sA, sT, tid);
    for (int i=tid;i<4096;i+=256) g_M[((size_t)b*3+2)*4096 + i] = sR[i];
    #undef GB
}

// =====================================================================
// K4: common branch: Y = M_c @ (ni+ne) tile ; LN ; FFN ; residual
// grid (1024, 4), block 256, 64 pixels/block. smem ~104KB -> 2 CTA/SM.
// =====================================================================
#define APL_SMEM_FLOATS 26560

__global__ void __launch_bounds__(256) apply_common_kernel(
    const float* __restrict__ lnw, const float* __restrict__ lnb,
    const float* __restrict__ W1g, const float* __restrict__ b1g,
    const float* __restrict__ W2g, const float* __restrict__ b2g,
    float* __restrict__ outp)
{
    extern __shared__ float sm[];
    float* sA  = sm;
    float* sX  = sm + 8704;
    float* sY  = sm + 13056;
    float* sW  = sm + 17408;
    float* sb1 = sm + 26112;
    float* sb2 = sm + 26240;
    float* slw = sm + 26304;
    float* slb = sm + 26368;
    float* smu = sm + 26432;
    float* srs = sm + 26496;

    int b = blockIdx.y;
    int p0 = blockIdx.x * 64;
    int tid = threadIdx.x, ty = tid>>4, tx = tid&15;

    const float* Mg = g_M + ((size_t)b*3+0)*4096;
    for (int i=tid;i<4096;i+=256) sA[(i>>6)*68 + (i&63)] = Mg[i];
    for (int i=tid;i<8192;i+=256) sW[(i>>6)*68 + (i&63)] = W1g[i];
    if (tid < 128) sb1[tid] = b1g[tid];
    if (tid < 64){ sb2[tid]=b2g[tid]; slw[tid]=lnw[tid]; slb[tid]=lnb[tid]; }
    {
        int row = tid>>2, cb = (tid&3)*16;
        const float* pi = g_ni + ((size_t)(b*C64+row))*HW + p0 + cb;
        const float* pe = g_ne + ((size_t)(b*C64+row))*HW + p0 + cb;
        #pragma unroll
        for (int j=0;j<16;j+=4){
            float4 a = *(const float4*)&pi[j];
            float4 e = *(const float4*)&pe[j];
            sX[row*68+cb+j+0]=a.x+e.x; sX[row*68+cb+j+1]=a.y+e.y;
            sX[row*68+cb+j+2]=a.z+e.z; sX[row*68+cb+j+3]=a.w+e.w;
        }
    }
    __syncthreads();
    // GEMM1: Y = M @ X
    {
        float acc[4][4] = {};
        for (int k=0;k<64;k++){
            float4 xv = *(const float4*)&sX[k*68 + tx*4];
            float x4[4] = {xv.x,xv.y,xv.z,xv.w};
            #pragma unroll
            for (int ii=0;ii<4;ii++){
                float m = sA[(ty*4+ii)*68 + k];
                #pragma unroll
                for (int jj=0;jj<4;jj++) acc[ii][jj] += m*x4[jj];
            }
        }
        __syncthreads();
        #pragma unroll
        for (int ii=0;ii<4;ii++)
            #pragma unroll
            for (int jj=0;jj<4;jj++)
                sY[(ty*4+ii)*68 + tx*4+jj] = acc[ii][jj];
    }
    __syncthreads();
    if (tid < 64){
        float s=0.f, ss=0.f;
        for (int c=0;c<64;c++){ float v = sY[c*68+tid]; s += v; ss += v*v; }
        float mu = s*(1.f/64.f);
        float var = ss*(1.f/64.f) - mu*mu;
        smu[tid] = mu; srs[tid] = rsqrtf(var + EPSF);
    }
    __syncthreads();
    for (int i=tid;i<4096;i+=256){
        int c = i>>6, px = i&63;
        sX[c*68+px] = (sY[c*68+px]-smu[px])*srs[px]*slw[c] + slb[c];
    }
    __syncthreads();
    // GEMM2: H = gelu(W1 @ Z + b1) -> into sA
    {
        float acc[8][4] = {};
        for (int k=0;k<64;k++){
            float4 zv = *(const float4*)&sX[k*68 + tx*4];
            float z4[4] = {zv.x,zv.y,zv.z,zv.w};
            #pragma unroll
            for (int rr=0;rr<8;rr++){
                float w = sW[(ty*8+rr)*68 + k];
                #pragma unroll
                for (int jj=0;jj<4;jj++) acc[rr][jj] += w*z4[jj];
            }
        }
        #pragma unroll
        for (int rr=0;rr<8;rr++)
            #pragma unroll
            for (int jj=0;jj<4;jj++){
                float h = acc[rr][jj] + sb1[ty*8+rr];
                sA[(ty*8+rr)*68 + tx*4+jj] = 0.5f*h*(1.f + erff(h*0.70710678118654752f));
            }
    }
    __syncthreads();
    // reload sW with W2 (64x128, pitch 132)
    for (int i=tid;i<8192;i+=256) sW[(i>>7)*132 + (i&127)] = W2g[i];
    __syncthreads();
    // GEMM3 + bias + residual + store
    {
        float acc[4][4] = {};
        for (int k=0;k<128;k++){
            float4 hv = *(const float4*)&sA[k*68 + tx*4];
            float h4[4] = {hv.x,hv.y,hv.z,hv.w};
            #pragma unroll
            for (int ii=0;ii<4;ii++){
                float w = sW[(ty*4+ii)*132 + k];
                #pragma unroll
                for (int jj=0;jj<4;jj++) acc[ii][jj] += w*h4[jj];
            }
        }
        #pragma unroll
        for (int ii=0;ii<4;ii++){
            int row = ty*4+ii;
            float4 o;
            o.x = acc[ii][0] + sb2[row] + sY[row*68 + tx*4+0];
            o.y = acc[ii][1] + sb2[row] + sY[row*68 + tx*4+1];
            o.z = acc[ii][2] + sb2[row] + sY[row*68 + tx*4+2];
            o.w = acc[ii][3] + sb2[row] + sY[row*68 + tx*4+3];
            *(float4*)&outp[((size_t)(b*C64+row))*HW + p0 + tx*4] = o;
        }
    }
}

// =====================================================================
// K5: diff branch: Y = M_id @ ni + M_ed @ ne (two staged passes)
// =====================================================================
__global__ void __launch_bounds__(256) apply_diff_kernel(
    const float* __restrict__ lnw, const float* __restrict__ lnb,
    const float* __restrict__ W1g, const float* __restrict__ b1g,
    const float* __restrict__ W2g, const float* __restrict__ b2g,
    float* __restrict__ outp)
{
    extern __shared__ float sm[];
    float* sA  = sm;
    float* sX  = sm + 8704;
    float* sY  = sm + 13056;
    float* sW  = sm + 17408;
    float* sb1 = sm + 26112;
    float* sb2 = sm + 26240;
    float* slw = sm + 26304;
    float* slb = sm + 26368;
    float* smu = sm + 26432;
    float* srs = sm + 26496;

    int b = blockIdx.y;
    int p0 = blockIdx.x * 64;
    int tid = threadIdx.x, ty = tid>>4, tx = tid&15;

    const float* Mi = g_M + ((size_t)b*3+1)*4096;
    const float* Me = g_M + ((size_t)b*3+2)*4096;
    for (int i=tid;i<4096;i+=256){
        int r = i>>6, k = i&63;
        sA[r*132 + k]      = Mi[i];
        sA[r*132 + 64 + k] = Me[i];
    }
    for (int i=tid;i<8192;i+=256) sW[(i>>6)*68 + (i&63)] = W1g[i];
    if (tid < 128) sb1[tid] = b1g[tid];
    if (tid < 64){ sb2[tid]=b2g[tid]; slw[tid]=lnw[tid]; slb[tid]=lnb[tid]; }
    // load ni tile
    {
        int row = tid>>2, cb = (tid&3)*16;
        const float* p = g_ni + ((size_t)(b*C64+row))*HW + p0 + cb;
        #pragma unroll
        for (int j=0;j<16;j+=4){
            float4 a = *(const float4*)&p[j];
            sX[row*68+cb+j+0]=a.x; sX[row*68+cb+j+1]=a.y;
            sX[row*68+cb+j+2]=a.z; sX[row*68+cb+j+3]=a.w;
        }
    }
    __syncthreads();
    float acc[4][4] = {};
    // GEMM1a: acc = M_id @ ni
    for (int k=0;k<64;k++){
        float4 xv = *(const float4*)&sX[k*68 + tx*4];
        float x4[4] = {xv.x,xv.y,xv.z,xv.w};
        #pragma unroll
        for (int ii=0;ii<4;ii++){
            float m = sA[(ty*4+ii)*132 + k];
            #pragma unroll
            for (int jj=0;jj<4;jj++) acc[ii][jj] += m*x4[jj];
        }
    }
    __syncthreads();
    // load ne tile
    {
        int row = tid>>2, cb = (tid&3)*16;
        const float* p = g_ne + ((size_t)(b*C64+row))*HW + p0 + cb;
        #pragma unroll
        for (int j=0;j<16;j+=4){
            float4 a = *(const float4*)&p[j];
            sX[row*68+cb+j+0]=a.x; sX[row*68+cb+j+1]=a.y;
            sX[row*68+cb+j+2]=a.z; sX[row*68+cb+j+3]=a.w;
        }
    }
    __syncthreads();
    // GEMM1b: acc += M_ed @ ne
    for (int k=0;k<64;k++){
        float4 xv = *(const float4*)&sX[k*68 + tx*4];
        float x4[4] = {xv.x,xv.y,xv.z,xv.w};
        #pragma unroll
        for (int ii=0;ii<4;ii++){
            float m = sA[(ty*4+ii)*132 + 64 + k];
            #pragma unroll
            for (int jj=0;jj<4;jj++) acc[ii][jj] += m*x4[jj];
        }
    }
    __syncthreads();
    #pragma unroll
    for (int ii=0;ii<4;ii++)
        #pragma unroll
        for (int jj=0;jj<4;jj++)
            sY[(ty*4+ii)*68 + tx*4+jj] = acc[ii][jj];
    __syncthreads();
    if (tid < 64){
        float s=0.f, ss=0.f;
        for (int c=0;c<64;c++){ float v = sY[c*68+tid]; s += v; ss += v*v; }
        float mu = s*(1.f/64.f);
        float var = ss*(1.f/64.f) - mu*mu;
        smu[tid] = mu; srs[tid] = rsqrtf(var + EPSF);
    }
    __syncthreads();
    for (int i=tid;i<4096;i+=256){
        int c = i>>6, px = i&63;
        sX[c*68+px] = (sY[c*68+px]-smu[px])*srs[px]*slw[c] + slb[c];
    }
    __syncthreads();
    // GEMM2: H = gelu(W1 @ Z + b1) -> sA
    {
        float a2[8][4] = {};
        for (int k=0;k<64;k++){
            float4 zv = *(const float4*)&sX[k*68 + tx*4];
            float z4[4] = {zv.x,zv.y,zv.z,zv.w};
            #pragma unroll
            for (int rr=0;rr<8;rr++){
                float w = sW[(ty*8+rr)*68 + k];
                #pragma unroll
                for (int jj=0;jj<4;jj++) a2[rr][jj] += w*z4[jj];
            }
        }
        #pragma unroll
        for (int rr=0;rr<8;rr++)
            #pragma unroll
            for (int jj=0;jj<4;jj++){
                float h = a2[rr][jj] + sb1[ty*8+rr];
                sA[(ty*8+rr)*68 + tx*4+jj] = 0.5f*h*(1.f + erff(h*0.70710678118654752f));
            }
    }
    __syncthreads();
    for (int i=tid;i<8192;i+=256) sW[(i>>7)*132 + (i&127)] = W2g[i];
    __syncthreads();
    // GEMM3 + bias + residual + store
    {
        float a3[4][4] = {};
        for (int k=0;k<128;k++){
            float4 hv = *(const float4*)&sA[k*68 + tx*4];
            float h4[4] = {hv.x,hv.y,hv.z,hv.w};
            #pragma unroll
            for (int ii=0;ii<4;ii++){
                float w = sW[(ty*4+ii)*132 + k];
                #pragma unroll
                for (int jj=0;jj<4;jj++) a3[ii][jj] += w*h4[jj];
            }
        }
        #pragma unroll
        for (int ii=0;ii<4;ii++){
            int row = ty*4+ii;
            float4 o;
            o.x = a3[ii][0] + sb2[row] + sY[row*68 + tx*4+0];
            o.y = a3[ii][1] + sb2[row] + sY[row*68 + tx*4+1];
            o.z = a3[ii][2] + sb2[row] + sY[row*68 + tx*4+2];
            o.w = a3[ii][3] + sb2[row] + sY[row*68 + tx*4+3];
            *(float4*)&outp[((size_t)(b*C64+row))*HW + p0 + tx*4] = o;
        }
    }
}

// =====================================================================
extern "C" void kernel_launch(void* const* d_in, const int* in_sizes, int n_in,
                              void* d_out, int out_size)
{
    (void)in_sizes; (void)n_in; (void)out_size;
    const float* image  = (const float*)d_in[0];
    const float* event_ = (const float*)d_in[1];
    const float* Wq_c = (const float*)d_in[2];
    const float* Wk_c = (const float*)d_in[3];
    const float* Wv_c = (const float*)d_in[4];
    const float* temp_c = (const float*)d_in[5];
    const float* Wq_d = (const float*)d_in[6];
    const float* Wk_d = (const float*)d_in[7];
    const float* Wv_d = (const float*)d_in[8];
    const float* temp_d = (const float*)d_in[9];
    const float* ln_img_w = (const float*)d_in[10];
    const float* ln_img_b = (const float*)d_in[11];
    const float* ln_evt_w = (const float*)d_in[12];
    const float* ln_evt_b = (const float*)d_in[13];
    const float* ln_com_w = (const float*)d_in[14];
    const float* ln_com_b = (const float*)d_in[15];
    const float* ln_dif_w = (const float*)d_in[16];
    const float* ln_dif_b = (const float*)d_in[17];
    const float* ln1_w = (const float*)d_in[18];
    const float* ln1_b = (const float*)d_in[19];
    const float* ln2_w = (const float*)d_in[20];
    const float* ln2_b = (const float*)d_in[21];
    const float* fc1c_w = (const float*)d_in[22];
    const float* fc1c_b = (const float*)d_in[23];
    const float* fc2c_w = (const float*)d_in[24];
    const float* fc2c_b = (const float*)d_in[25];
    const float* fc1d_w = (const float*)d_in[26];
    const float* fc1d_b = (const float*)d_in[27];
    const float* fc2d_w = (const float*)d_in[28];
    const float* fc2d_b = (const float*)d_in[29];
    const float* proj1_w = (const float*)d_in[30];
    const float* proj2_w = (const float*)d_in[31];

    float* outc = (float*)d_out;
    float* outd = outc + (size_t)BATCH*C64*HW;

    const int SM3 = (4096*5 + 1024*2 + 64*3) * sizeof(float);
    const int SMA = APL_SMEM_FLOATS * sizeof(float);

    cudaFuncSetAttribute(smallmath_kernel,    cudaFuncAttributeMaxDynamicSharedMemorySize, SM3);
    cudaFuncSetAttribute(apply_common_kernel, cudaFuncAttributeMaxDynamicSharedMemorySize, SMA);
    cudaFuncSetAttribute(apply_diff_kernel,   cudaFuncAttributeMaxDynamicSharedMemorySize, SMA);

    ln_kernel<<<BATCH*(HW/256), 256>>>(image, event_,
        ln_img_w, ln_img_b, ln_evt_w, ln_evt_b,
        ln_com_w, ln_com_b, ln_dif_w, ln_dif_b);

    dim3 g2(GK_KSPLIT, 4, BATCH);
    gram_mma_kernel<<<g2, 256>>>();

    smallmath_kernel<<<BATCH, 256, SM3>>>(Wq_c, Wk_c, Wv_c, temp_c,
                                          Wq_d, Wk_d, Wv_d, temp_d,
                                          proj1_w, proj2_w);

    dim3 g4(HW/64, BATCH);
    apply_common_kernel<<<g4, 256, SMA>>>(ln1_w, ln1_b, fc1c_w, fc1c_b,
                                          fc2c_w, fc2c_b, outc);
    apply_diff_kernel<<<g4, 256, SMA>>>(ln2_w, ln2_b, fc1d_w, fc1d_b,
                                        fc2d_w, fc2d_b, outd);
}

// round 8
// speedup vs baseline: 1.3364x; 1.1787x over previous
#include <cuda_runtime.h>
#include <cuda_bf16.h>
#include <math.h>
#include <stdint.h>

#define BATCH 4
#define C64   64
#define HW    65536
#define HEADS 4
#define HID   128
#define EPSF  1e-5f

#define TOT (BATCH*C64*HW)

// ---------------- scratch (device globals; no allocs) ----------------
__device__ float g_ni[TOT];
__device__ float g_ne[TOT];
__device__ float g_nc[TOT];
__device__ float g_nd[TOT];
__device__ float g_gram256[BATCH*256*256];
__device__ float g_M[BATCH*3*C64*C64];

// ======================= helpers ========================
__device__ __forceinline__ uint32_t smem_u32(const void* p){
    uint32_t a;
    asm("{ .reg .u64 t; cvta.to.shared.u64 t, %1; cvt.u32.u64 %0, t; }" : "=r"(a) : "l"(p));
    return a;
}
__device__ __forceinline__ void ldm_x4(uint32_t* r, uint32_t addr){
    asm volatile("ldmatrix.sync.aligned.m8n8.x4.shared.b16 {%0,%1,%2,%3}, [%4];"
        : "=r"(r[0]), "=r"(r[1]), "=r"(r[2]), "=r"(r[3]) : "r"(addr));
}
__device__ __forceinline__ void ldm_t4(uint32_t* r, uint32_t addr){
    asm volatile("ldmatrix.sync.aligned.m8n8.x4.trans.shared.b16 {%0,%1,%2,%3}, [%4];"
        : "=r"(r[0]), "=r"(r[1]), "=r"(r[2]), "=r"(r[3]) : "r"(addr));
}
__device__ __forceinline__ void mma_bf16(float& d0, float& d1, float& d2, float& d3,
        uint32_t a0, uint32_t a1, uint32_t a2, uint32_t a3,
        uint32_t b0, uint32_t b1){
    asm volatile("mma.sync.aligned.m16n8k16.row.col.f32.bf16.bf16.f32 "
        "{%0,%1,%2,%3}, {%4,%5,%6,%7}, {%8,%9}, {%0,%1,%2,%3};"
        : "+f"(d0), "+f"(d1), "+f"(d2), "+f"(d3)
        : "r"(a0), "r"(a1), "r"(a2), "r"(a3), "r"(b0), "r"(b1));
}
// 3-pass hi/lo mma into one fp32 accumulator group
#define MMA3(ACC, AH, AL, BH0, BH1, BL0, BL1) do { \
    mma_bf16((ACC)[0],(ACC)[1],(ACC)[2],(ACC)[3], (AH)[0],(AH)[1],(AH)[2],(AH)[3], (BH0),(BH1)); \
    mma_bf16((ACC)[0],(ACC)[1],(ACC)[2],(ACC)[3], (AH)[0],(AH)[1],(AH)[2],(AH)[3], (BL0),(BL1)); \
    mma_bf16((ACC)[0],(ACC)[1],(ACC)[2],(ACC)[3], (AL)[0],(AL)[1],(AL)[2],(AL)[3], (BH0),(BH1)); \
} while(0)

__device__ __forceinline__ void split2(float a, float b, uint32_t& h, uint32_t& l){
    __nv_bfloat16 ha=__float2bfloat16(a), hb=__float2bfloat16(b);
    float ra = a-__bfloat162float(ha), rb = b-__bfloat162float(hb);
    h = (uint32_t)__bfloat16_as_ushort(ha) | ((uint32_t)__bfloat16_as_ushort(hb)<<16);
    l = (uint32_t)__bfloat16_as_ushort(__float2bfloat16(ra))
      | ((uint32_t)__bfloat16_as_ushort(__float2bfloat16(rb))<<16);
}
__device__ __forceinline__ void split4(float4 v, uint2& hh, uint2& ll){
    split2(v.x, v.y, hh.x, ll.x);
    split2(v.z, v.w, hh.y, ll.y);
}
__device__ __forceinline__ float gelu_f(float h){
    return 0.5f*h*(1.f + erff(h*0.70710678118654752f));
}

// =====================================================================
// K1: channel LayerNorm for ni/ne/nc/nd  (+ zero gram accumulator)
// =====================================================================
__global__ void __launch_bounds__(256) ln_kernel(
    const float* __restrict__ img, const float* __restrict__ evt,
    const float* __restrict__ wi, const float* __restrict__ bi,
    const float* __restrict__ we, const float* __restrict__ be,
    const float* __restrict__ wc, const float* __restrict__ bc,
    const float* __restrict__ wd, const float* __restrict__ bd)
{
    if (blockIdx.x < 256) {
        int base = blockIdx.x * 1024 + threadIdx.x * 4;
        g_gram256[base+0] = 0.f; g_gram256[base+1] = 0.f;
        g_gram256[base+2] = 0.f; g_gram256[base+3] = 0.f;
    }
    int b  = blockIdx.x >> 8;
    int p  = ((blockIdx.x & 255) << 8) + threadIdx.x;
    const float* ip = img + (size_t)b*C64*HW + p;
    const float* ep = evt + (size_t)b*C64*HW + p;

    float si=0.f, se=0.f, sii=0.f, see=0.f, sie=0.f;
    #pragma unroll 8
    for (int c=0;c<C64;c++){
        float iv = ip[c*HW], ev = ep[c*HW];
        si += iv; se += ev; sii += iv*iv; see += ev*ev; sie += iv*ev;
    }
    const float inv64 = 1.f/64.f;
    float mi = si*inv64, me = se*inv64;
    float vi = sii*inv64 - mi*mi;
    float ve = see*inv64 - me*me;
    float mc = (si+se)*inv64, md = (si-se)*inv64;
    float vc = (sii + 2.f*sie + see)*inv64 - mc*mc;
    float vd = (sii - 2.f*sie + see)*inv64 - md*md;
    float ri = rsqrtf(vi+EPSF), re = rsqrtf(ve+EPSF);
    float rc = rsqrtf(vc+EPSF), rd = rsqrtf(vd+EPSF);

    size_t ob = (size_t)b*C64*HW + p;
    #pragma unroll 8
    for (int c=0;c<C64;c++){
        float iv = ip[c*HW], ev = ep[c*HW];
        g_ni[ob + (size_t)c*HW] = (iv-mi)*ri*wi[c] + bi[c];
        g_ne[ob + (size_t)c*HW] = (ev-me)*re*we[c] + be[c];
        g_nc[ob + (size_t)c*HW] = (iv+ev-mc)*rc*wc[c] + bc[c];
        g_nd[ob + (size_t)c*HW] = (iv-ev-md)*rd*wd[c] + bd[c];
    }
}

// =====================================================================
// K2: stacked Gram via mma.sync bf16 hi/lo (3 passes), fp32 accum.
// =====================================================================
#define GK_KSPLIT 32
#define GK_KRANGE (HW/GK_KSPLIT)
#define GK_KC     32
#define GK_NCH    (GK_KRANGE/GK_KC)
#define SPITCH    40

__global__ void __launch_bounds__(256) gram_mma_kernel()
{
    __shared__ __align__(16) unsigned short sAhi[128*SPITCH];
    __shared__ __align__(16) unsigned short sAlo[128*SPITCH];
    __shared__ __align__(16) unsigned short sBhi[128*SPITCH];
    __shared__ __align__(16) unsigned short sBlo[128*SPITCH];

    int tid = threadIdx.x;
    int wid = tid >> 5, lane = tid & 31;
    int ks = blockIdx.x, tileid = blockIdx.y, b = blockIdx.z;
    int m0 = (tileid >> 1) * 128;
    int n0 = (tileid & 1) * 128;
    int warp_m = (wid >> 1) * 32;
    int warp_n = (wid & 1) * 64;

    const float* tens[4] = {g_ni, g_ne, g_nc, g_nd};

    int lr = tid >> 1;
    int lc = (tid & 1) * 16;
    const float* srcA = tens[(m0+lr)>>6] + ((size_t)(b*C64) + ((m0+lr)&63))*HW + (size_t)ks*GK_KRANGE + lc;
    const float* srcB = tens[(n0+lr)>>6] + ((size_t)(b*C64) + ((n0+lr)&63))*HW + (size_t)ks*GK_KRANGE + lc;

    uint32_t aHi = smem_u32(sAhi), aLo = smem_u32(sAlo);
    uint32_t bHi = smem_u32(sBhi), bLo = smem_u32(sBlo);

    int rowA = warp_m + (lane & 15);
    int colA = (lane >> 4) * 8;
    uint32_t offA = (uint32_t)(rowA*SPITCH + colA) * 2;
    int rowB = warp_n + (lane & 7) + ((lane >> 4) & 1) * 8;
    int colB = ((lane >> 3) & 1) * 8;
    uint32_t offB = (uint32_t)(rowB*SPITCH + colB) * 2;

    float acc[2][8][4];
    #pragma unroll
    for (int i=0;i<2;i++)
        #pragma unroll
        for (int j=0;j<8;j++)
            #pragma unroll
            for (int k=0;k<4;k++) acc[i][j][k] = 0.f;

    for (int t = 0; t < GK_NCH; t++) {
        __syncthreads();
        int kc = t * GK_KC;
        {
            const float* pa = srcA + kc;
            const float* pb = srcB + kc;
            unsigned short* dAh = sAhi + lr*SPITCH + lc;
            unsigned short* dAl = sAlo + lr*SPITCH + lc;
            unsigned short* dBh = sBhi + lr*SPITCH + lc;
            unsigned short* dBl = sBlo + lr*SPITCH + lc;
            #pragma unroll
            for (int j=0;j<16;j+=4){
                uint2 hh, ll;
                split4(*(const float4*)&pa[j], hh, ll);
                *(uint2*)&dAh[j] = hh; *(uint2*)&dAl[j] = ll;
                split4(*(const float4*)&pb[j], hh, ll);
                *(uint2*)&dBh[j] = hh; *(uint2*)&dBl[j] = ll;
            }
        }
        __syncthreads();
        #pragma unroll
        for (int k16 = 0; k16 < GK_KC; k16 += 16) {
            uint32_t kb = (uint32_t)(k16 * 2);
            uint32_t Ah0[4], Ah1[4], Al0[4], Al1[4];
            ldm_x4(Ah0, aHi + offA + kb);
            ldm_x4(Ah1, aHi + offA + kb + 16*SPITCH*2);
            ldm_x4(Al0, aLo + offA + kb);
            ldm_x4(Al1, aLo + offA + kb + 16*SPITCH*2);
            #pragma unroll
            for (int np = 0; np < 4; np++) {
                uint32_t Bh[4], Bl[4];
                uint32_t ob = offB + kb + (uint32_t)(np*16*SPITCH*2);
                ldm_x4(Bh, bHi + ob);
                ldm_x4(Bl, bLo + ob);
                int n2 = np*2;
                MMA3(acc[0][n2],   Ah0, Al0, Bh[0],Bh[1], Bl[0],Bl[1]);
                MMA3(acc[0][n2+1], Ah0, Al0, Bh[2],Bh[3], Bl[2],Bl[3]);
                MMA3(acc[1][n2],   Ah1, Al1, Bh[0],Bh[1], Bl[0],Bl[1]);
                MMA3(acc[1][n2+1], Ah1, Al1, Bh[2],Bh[3], Bl[2],Bl[3]);
            }
        }
    }

    float* G = g_gram256 + (size_t)b*65536;
    int rbase = m0 + warp_m + (lane >> 2);
    int cbase = n0 + warp_n + (lane & 3)*2;
    #pragma unroll
    for (int i=0;i<2;i++){
        #pragma unroll
        for (int ns=0;ns<8;ns++){
            int rr = rbase + i*16;
            int cc = cbase + ns*8;
            atomicAdd(&G[rr*256 + cc],       acc[i][ns][0]);
            atomicAdd(&G[rr*256 + cc + 1],   acc[i][ns][1]);
            atomicAdd(&G[(rr+8)*256 + cc],   acc[i][ns][2]);
            atomicAdd(&G[(rr+8)*256 + cc+1], acc[i][ns][3]);
        }
    }
}

// =====================================================================
// K3: tiny per-batch math -> M_c, M_id, M_ed. grid 4, block 256.
// =====================================================================
__device__ __forceinline__ void ld_mat(float* s, const float* __restrict__ g, int tid){
    for (int i=tid; i<4096; i+=256) s[i] = g[i];
}
__device__ __forceinline__ void ld_matg(float* s, const float* __restrict__ g, int tid){
    for (int i=tid; i<4096; i+=256) s[i] = g[(i>>6)*256 + (i&63)];
}
__device__ __forceinline__ void mm64_nn(float* Cm, const float* A, const float* Bm, int tid){
    int ty = tid>>4, tx = tid&15;
    float acc[4][4] = {};
    for (int k=0;k<64;k++){
        float4 bv = *(const float4*)&Bm[k*64 + tx*4];
        float b4[4] = {bv.x,bv.y,bv.z,bv.w};
        #pragma unroll
        for (int ii=0;ii<4;ii++){
            float a = A[(ty*4+ii)*64 + k];
            #pragma unroll
            for (int jj=0;jj<4;jj++) acc[ii][jj] += a*b4[jj];
        }
    }
    #pragma unroll
    for (int ii=0;ii<4;ii++)
        #pragma unroll
        for (int jj=0;jj<4;jj++)
            Cm[(ty*4+ii)*64 + tx*4+jj] = acc[ii][jj];
    __syncthreads();
}
__device__ __forceinline__ void mm64_nt(float* Cm, const float* A, const float* Bm, int tid){
    int ty = tid>>4, tx = tid&15;
    float acc[4][4] = {};
    for (int k=0;k<64;k++){
        float a4[4], b4[4];
        #pragma unroll
        for (int ii=0;ii<4;ii++) a4[ii] = A[(ty*4+ii)*64 + k];
        #pragma unroll
        for (int jj=0;jj<4;jj++) b4[jj] = Bm[(tx*4+jj)*64 + k];
        #pragma unroll
        for (int ii=0;ii<4;ii++)
            #pragma unroll
            for (int jj=0;jj<4;jj++) acc[ii][jj] += a4[ii]*b4[jj];
    }
    #pragma unroll
    for (int ii=0;ii<4;ii++)
        #pragma unroll
        for (int jj=0;jj<4;jj++)
            Cm[(ty*4+ii)*64 + tx*4+jj] = acc[ii][jj];
    __syncthreads();
}
__device__ __forceinline__ void rownorm_inv(float* inv, const float* T, const float* Wm, int tid){
    if (tid < 64){
        float s = 0.f;
        for (int k=0;k<64;k++) s += T[tid*64+k]*Wm[tid*64+k];
        inv[tid] = 1.f / fmaxf(sqrtf(fmaxf(s, 0.f)), 1e-12f);
    }
    __syncthreads();
}
__device__ __forceinline__ void attn_softmax(float* out, const float* raw,
        const float* invq, const float* invk, const float* __restrict__ temp, int tid){
    if (tid < 64){
        int head = tid >> 4, base = head*16;
        float t = temp[head];
        float l[16]; float mx = -1e30f;
        #pragma unroll
        for (int s=0;s<16;s++){
            l[s] = raw[tid*64 + base + s] * invq[tid] * invk[base+s] * t;
            mx = fmaxf(mx, l[s]);
        }
        float sum = 0.f;
        #pragma unroll
        for (int s=0;s<16;s++){ l[s] = expf(l[s]-mx); sum += l[s]; }
        float r = 1.f/sum;
        #pragma unroll
        for (int s=0;s<16;s++) out[tid*16+s] = l[s]*r;
    }
    __syncthreads();
}
__device__ __forceinline__ void bdv(float* Cm, const float* at, const float* Wv, int tid){
    int ty = tid>>4, tx = tid&15;
    float acc[4][4] = {};
    for (int s=0;s<16;s++){
        #pragma unroll
        for (int ii=0;ii<4;ii++){
            int row = ty*4+ii; int head = row >> 4;
            float a = at[row*16 + s];
            float4 wv = *(const float4*)&Wv[(head*16+s)*64 + tx*4];
            acc[ii][0] += a*wv.x; acc[ii][1] += a*wv.y;
            acc[ii][2] += a*wv.z; acc[ii][3] += a*wv.w;
        }
    }
    #pragma unroll
    for (int ii=0;ii<4;ii++)
        #pragma unroll
        for (int jj=0;jj<4;jj++)
            Cm[(ty*4+ii)*64 + tx*4+jj] = acc[ii][jj];
    __syncthreads();
}

__global__ void __launch_bounds__(256) smallmath_kernel(
    const float* __restrict__ Wq_c, const float* __restrict__ Wk_c, const float* __restrict__ Wv_c,
    const float* __restrict__ temp_c,
    const float* __restrict__ Wq_d, const float* __restrict__ Wk_d, const float* __restrict__ Wv_d,
    const float* __restrict__ temp_d,
    const float* __restrict__ proj1, const float* __restrict__ proj2)
{
    extern __shared__ float sm[];
    float* sA   = sm;
    float* sB   = sA + 4096;
    float* sG   = sB + 4096;
    float* sT   = sG + 4096;
    float* sR   = sT + 4096;
    float* aA   = sR + 4096;
    float* aB   = aA + 1024;
    float* invq  = aB + 1024;
    float* invk1 = invq + 64;
    float* invk2 = invk1 + 64;

    int b = blockIdx.x;
    int tid = threadIdx.x;
    #define GB(bi,bj) (g_gram256 + (size_t)b*65536 + (bi)*64*256 + (bj)*64)

    // ---------- common branch ----------
    ld_mat(sA, Wq_c, tid); ld_matg(sG, GB(2,2), tid); __syncthreads();
    mm64_nn(sT, sA, sG, tid);
    rownorm_inv(invq, sT, sA, tid);
    ld_mat(sB, Wk_c, tid); ld_matg(sG, GB(0,0), tid); __syncthreads();
    mm64_nn(sT, sB, sG, tid);
    rownorm_inv(invk1, sT, sB, tid);
    ld_matg(sG, GB(1,1), tid); __syncthreads();
    mm64_nn(sT, sB, sG, tid);
    rownorm_inv(invk2, sT, sB, tid);
    ld_matg(sG, GB(2,0), tid); __syncthreads();
    mm64_nn(sT, sA, sG, tid);
    mm64_nt(sR, sT, sB, tid);
    attn_softmax(aA, sR, invq, invk1, temp_c, tid);
    ld_matg(sG, GB(2,1), tid); __syncthreads();
    mm64_nn(sT, sA, sG, tid);
    mm64_nt(sR, sT, sB, tid);
    attn_softmax(aB, sR, invq, invk2, temp_c, tid);
    if (tid < 64){
        #pragma unroll
        for (int s=0;s<16;s++) aA[tid*16+s] *= aB[tid*16+s];
    }
    __syncthreads();
    ld_mat(sB, Wv_c, tid); __syncthreads();
    bdv(sT, aA, sB, tid);
    ld_mat(sA, proj1, tid); __syncthreads();
    mm64_nn(sR, sA, sT, tid);
    for (int i=tid;i<4096;i+=256) g_M[((size_t)b*3+0)*4096 + i] = sR[i];
    __syncthreads();

    // ---------- differential branch ----------
    ld_mat(sA, Wq_d, tid); ld_matg(sG, GB(3,3), tid); __syncthreads();
    mm64_nn(sT, sA, sG, tid);
    rownorm_inv(invq, sT, sA, tid);
    ld_mat(sB, Wk_d, tid); ld_matg(sG, GB(0,0), tid); __syncthreads();
    mm64_nn(sT, sB, sG, tid);
    rownorm_inv(invk1, sT, sB, tid);
    ld_matg(sG, GB(1,1), tid); __syncthreads();
    mm64_nn(sT, sB, sG, tid);
    rownorm_inv(invk2, sT, sB, tid);
    ld_matg(sG, GB(3,0), tid); __syncthreads();
    mm64_nn(sT, sA, sG, tid);
    mm64_nt(sR, sT, sB, tid);
    attn_softmax(aA, sR, invq, invk1, temp_d, tid);
    ld_matg(sG, GB(3,1), tid); __syncthreads();
    mm64_nn(sT, sA, sG, tid);
    mm64_nt(sR, sT, sB, tid);
    attn_softmax(aB, sR, invq, invk2, temp_d, tid);
    ld_mat(sB, Wv_d, tid); ld_mat(sA, proj2, tid); __syncthreads();
    bdv(sT, aA, sB, tid);
    mm64_nn(sR, sA, sT, tid);
    for (int i=tid;i<4096;i+=256) g_M[((size_t)b*3+1)*4096 + i] = sR[i];
    __syncthreads();
    bdv(sT, aB, sB, tid);
    mm64_nn(sR, sA, sT, tid);
    for (int i=tid;i<4096;i+=256) g_M[((size_t)b*3+2)*4096 + i] = sR[i];
    #undef GB
}

// =====================================================================
// K4/K5: apply kernels with bf16 hi/lo HMMA GEMMs.
// Tile: 64 channels x 64 pixels per CTA; 8 warps.
// smem byte layout:
//  sAh 0       (18432)   A-operand hi: M (p72) -> W1 (p72, 128 rows) -> W2 (p136)
//  sAl 18432   (18432)
//  sXh 36864   (9216)    activations hi [k=64][px] pitch 72 (X then Z)
//  sXl 46080   (9216)
//  sHh 55296   (18432)   H hi [h=128][px] pitch 72
//  sHl 73728   (18432)
//  sY  92160   (17408)   fp32 [64][68]
//  misc 109568..111616
// =====================================================================
#define AP_SMEM_BYTES 111616

// shared epilogue stages (LN -> Z -> W1 load -> GEMM2 -> H -> W2 load -> GEMM3 -> out)
__device__ __forceinline__ void apply_tail(
    unsigned short* sAh, unsigned short* sAl,
    unsigned short* sXh, unsigned short* sXl,
    unsigned short* sHh, unsigned short* sHl,
    float* sY, float* sb1, float* sb2, float* slw, float* slb,
    float* smu, float* srs,
    uint32_t aH, uint32_t aL, uint32_t xH, uint32_t xL, uint32_t hH, uint32_t hL,
    const float* __restrict__ W1g, const float* __restrict__ W2g,
    float* __restrict__ outp, int b, int p0)
{
    int tid = threadIdx.x, w = tid>>5, lane = tid&31;
    int wc = (w>>1)*16, wpx = (w&1)*32;
    uint32_t offB = (uint32_t)((((lane&7)+((lane>>3)&1)*8)*72 + ((lane>>4)&1)*8)*2);

    // LN stats over channels per pixel
    if (tid < 64){
        float s=0.f, ss=0.f;
        for (int c=0;c<64;c++){ float v = sY[c*68+tid]; s += v; ss += v*v; }
        float mu = s*(1.f/64.f);
        float var = ss*(1.f/64.f) - mu*mu;
        smu[tid] = mu; srs[tid] = rsqrtf(var + EPSF);
    }
    __syncthreads();
    // Z -> sX (hi/lo), W1 -> sA (pitch 72, 128 rows x 64 k)
    for (int i=tid;i<2048;i+=256){
        int c = i>>5, px = (i&31)*2;
        float z0 = (sY[c*68+px  ]-smu[px  ])*srs[px  ]*slw[c] + slb[c];
        float z1 = (sY[c*68+px+1]-smu[px+1])*srs[px+1]*slw[c] + slb[c];
        uint32_t hh, ll; split2(z0, z1, hh, ll);
        *(uint32_t*)&sXh[c*72+px] = hh;
        *(uint32_t*)&sXl[c*72+px] = ll;
    }
    for (int i=tid;i<2048;i+=256){
        int r = i>>4, k4 = (i&15)*4;          // FIXED: 128 rows x 16 float4-groups
        uint2 hh, ll; split4(*(const float4*)&W1g[r*64+k4], hh, ll);
        *(uint2*)&sAh[r*72+k4] = hh;
        *(uint2*)&sAl[r*72+k4] = ll;
    }
    __syncthreads();

    // GEMM2: H[128h x 64px] = W1 @ Z, warp tile 32h x 32px
    {
        int wh = (w>>1)*32;
        float acc[2][4][4];
        #pragma unroll
        for (int m=0;m<2;m++)
            #pragma unroll
            for (int g=0;g<4;g++)
                #pragma unroll
                for (int k=0;k<4;k++) acc[m][g][k]=0.f;
        uint32_t offA2 = (uint32_t)(((wh+(lane&15))*72 + ((lane>>4)&1)*8)*2);
        #pragma unroll
        for (int k16=0;k16<4;k16++){
            uint32_t Ah0[4],Al0[4],Ah1[4],Al1[4];
            ldm_x4(Ah0, aH + offA2 + k16*32);
            ldm_x4(Al0, aL + offA2 + k16*32);
            ldm_x4(Ah1, aH + offA2 + k16*32 + 16*144);
            ldm_x4(Al1, aL + offA2 + k16*32 + 16*144);
            #pragma unroll
            for (int hf=0;hf<2;hf++){
                uint32_t Bh[4],Bl[4];
                uint32_t ob = offB + (uint32_t)(k16*16*144 + (wpx+hf*16)*2);
                ldm_t4(Bh, xH + ob); ldm_t4(Bl, xL + ob);
                int g0=hf*2, g1=hf*2+1;
                MMA3(acc[0][g0], Ah0, Al0, Bh[0],Bh[1], Bl[0],Bl[1]);
                MMA3(acc[0][g1], Ah0, Al0, Bh[2],Bh[3], Bl[2],Bl[3]);
                MMA3(acc[1][g0], Ah1, Al1, Bh[0],Bh[1], Bl[0],Bl[1]);
                MMA3(acc[1][g1], Ah1, Al1, Bh[2],Bh[3], Bl[2],Bl[3]);
            }
        }
        // bias + gelu + store H hi/lo [h][px]
        int hb = wh + (lane>>2);
        int pxb = wpx + (lane&3)*2;
        #pragma unroll
        for (int m=0;m<2;m++){
            int r0 = hb + m*16, r1 = r0 + 8;
            float bb0 = sb1[r0], bb1 = sb1[r1];
            #pragma unroll
            for (int g=0; g<4; g++){
                int px = pxb + g*8;
                float v0 = gelu_f(acc[m][g][0] + bb0);
                float v1 = gelu_f(acc[m][g][1] + bb0);
                float v2 = gelu_f(acc[m][g][2] + bb1);
                float v3 = gelu_f(acc[m][g][3] + bb1);
                uint32_t hh, ll;
                split2(v0, v1, hh, ll);
                *(uint32_t*)&sHh[r0*72+px] = hh; *(uint32_t*)&sHl[r0*72+px] = ll;
                split2(v2, v3, hh, ll);
                *(uint32_t*)&sHh[r1*72+px] = hh; *(uint32_t*)&sHl[r1*72+px] = ll;
            }
        }
    }
    __syncthreads();
    // W2 -> sA (pitch 136, 64 rows x 128 k)
    for (int i=tid;i<2048;i+=256){
        int r = i>>5, k4 = (i&31)*4;
        uint2 hh, ll; split4(*(const float4*)&W2g[r*128+k4], hh, ll);
        *(uint2*)&sAh[r*136+k4] = hh;
        *(uint2*)&sAl[r*136+k4] = ll;
    }
    __syncthreads();

    // GEMM3: O[64c x 64px] = W2 @ H (k=128), + bias + residual + store
    {
        float acc[4][4];
        #pragma unroll
        for (int g=0;g<4;g++)
            #pragma unroll
            for (int k=0;k<4;k++) acc[g][k]=0.f;
        uint32_t offA3 = (uint32_t)(((wc+(lane&15))*136 + ((lane>>4)&1)*8)*2);
        #pragma unroll
        for (int k16=0;k16<8;k16++){
            uint32_t Ah[4],Al[4];
            ldm_x4(Ah, aH + offA3 + k16*32);
            ldm_x4(Al, aL + offA3 + k16*32);
            #pragma unroll
            for (int hf=0;hf<2;hf++){
                uint32_t Bh[4],Bl[4];
                uint32_t ob = offB + (uint32_t)(k16*16*144 + (wpx+hf*16)*2);
                ldm_t4(Bh, hH + ob); ldm_t4(Bl, hL + ob);
                MMA3(acc[hf*2],   Ah, Al, Bh[0],Bh[1], Bl[0],Bl[1]);
                MMA3(acc[hf*2+1], Ah, Al, Bh[2],Bh[3], Bl[2],Bl[3]);
            }
        }
        int c0 = wc + (lane>>2);
        int pxb = wpx + (lane&3)*2;
        float bc0 = sb2[c0], bc1 = sb2[c0+8];
        #pragma unroll
        for (int g=0; g<4; g++){
            int px = pxb + g*8;
            float2 o;
            o.x = acc[g][0] + bc0 + sY[c0*68+px];
            o.y = acc[g][1] + bc0 + sY[c0*68+px+1];
            *(float2*)&outp[((size_t)(b*C64+c0))*HW + p0 + px] = o;
            o.x = acc[g][2] + bc1 + sY[(c0+8)*68+px];
            o.y = acc[g][3] + bc1 + sY[(c0+8)*68+px+1];
            *(float2*)&outp[((size_t)(b*C64+c0+8))*HW + p0 + px] = o;
        }
    }
}

__global__ void __launch_bounds__(256) apply_common_kernel(
    const float* __restrict__ lnw, const float* __restrict__ lnb,
    const float* __restrict__ W1g, const float* __restrict__ b1g,
    const float* __restrict__ W2g, const float* __restrict__ b2g,
    float* __restrict__ outp)
{
    extern __shared__ char smraw[];
    unsigned short* sAh = (unsigned short*)(smraw);
    unsigned short* sAl = (unsigned short*)(smraw + 18432);
    unsigned short* sXh = (unsigned short*)(smraw + 36864);
    unsigned short* sXl = (unsigned short*)(smraw + 46080);
    unsigned short* sHh = (unsigned short*)(smraw + 55296);
    unsigned short* sHl = (unsigned short*)(smraw + 73728);
    float* sY  = (float*)(smraw + 92160);
    float* sb1 = (float*)(smraw + 109568);
    float* sb2 = sb1 + 128;
    float* slw = sb2 + 64;
    float* slb = slw + 64;
    float* smu = slb + 64;
    float* srs = smu + 64;

    uint32_t aH = smem_u32(sAh), aL = smem_u32(sAl);
    uint32_t xH = smem_u32(sXh), xL = smem_u32(sXl);
    uint32_t hH = smem_u32(sHh), hL = smem_u32(sHl);

    int b = blockIdx.y, p0 = blockIdx.x*64;
    int tid = threadIdx.x, w = tid>>5, lane = tid&31;
    int wc = (w>>1)*16, wpx = (w&1)*32;

    if (tid < 128) sb1[tid] = b1g[tid];
    if (tid < 64){ sb2[tid]=b2g[tid]; slw[tid]=lnw[tid]; slb[tid]=lnb[tid]; }

    // M_c -> sA (pitch 72)
    const float* Mg = g_M + ((size_t)b*3+0)*4096;
    for (int i=tid;i<1024;i+=256){
        int r = i>>4, k4 = (i&15)*4;
        uint2 hh, ll; split4(*(const float4*)&Mg[r*64+k4], hh, ll);
        *(uint2*)&sAh[r*72+k4] = hh;
        *(uint2*)&sAl[r*72+k4] = ll;
    }
    // X = ni+ne -> sX [c][px] pitch 72
    for (int i=tid;i<1024;i+=256){
        int c = i>>4, px4 = (i&15)*4;
        const float* pi = g_ni + ((size_t)(b*C64+c))*HW + p0 + px4;
        const float* pe = g_ne + ((size_t)(b*C64+c))*HW + p0 + px4;
        float4 a = *(const float4*)pi;
        float4 e = *(const float4*)pe;
        float4 v = make_float4(a.x+e.x, a.y+e.y, a.z+e.z, a.w+e.w);
        uint2 hh, ll; split4(v, hh, ll);
        *(uint2*)&sXh[c*72+px4] = hh;
        *(uint2*)&sXl[c*72+px4] = ll;
    }
    __syncthreads();

    // GEMM1: Y = M @ X, warp tile 16c x 32px
    {
        float acc[4][4];
        #pragma unroll
        for (int g=0;g<4;g++)
            #pragma unroll
            for (int k=0;k<4;k++) acc[g][k]=0.f;
        uint32_t offA = (uint32_t)(((wc+(lane&15))*72 + ((lane>>4)&1)*8)*2);
        uint32_t offB = (uint32_t)((((lane&7)+((lane>>3)&1)*8)*72 + ((lane>>4)&1)*8)*2);
        #pragma unroll
        for (int k16=0;k16<4;k16++){
            uint32_t Ah[4],Al[4];
            ldm_x4(Ah, aH + offA + k16*32);
            ldm_x4(Al, aL + offA + k16*32);
            #pragma unroll
            for (int hf=0;hf<2;hf++){
                uint32_t Bh[4],Bl[4];
                uint32_t ob = offB + (uint32_t)(k16*16*144 + (wpx+hf*16)*2);
                ldm_t4(Bh, xH + ob); ldm_t4(Bl, xL + ob);
                MMA3(acc[hf*2],   Ah, Al, Bh[0],Bh[1], Bl[0],Bl[1]);
                MMA3(acc[hf*2+1], Ah, Al, Bh[2],Bh[3], Bl[2],Bl[3]);
            }
        }
        int c0 = wc + (lane>>2);
        int pxb = wpx + (lane&3)*2;
        #pragma unroll
        for (int g=0; g<4; g++){
            int px = pxb + g*8;
            *(float2*)&sY[c0*68+px]     = make_float2(acc[g][0], acc[g][1]);
            *(float2*)&sY[(c0+8)*68+px] = make_float2(acc[g][2], acc[g][3]);
        }
    }
    __syncthreads();
    apply_tail(sAh,sAl,sXh,sXl,sHh,sHl,sY,sb1,sb2,slw,slb,smu,srs,
               aH,aL,xH,xL,hH,hL, W1g, W2g, outp, b, p0);
}

__global__ void __launch_bounds__(256) apply_diff_kernel(
    const float* __restrict__ lnw, const float* __restrict__ lnb,
    const float* __restrict__ W1g, const float* __restrict__ b1g,
    const float* __restrict__ W2g, const float* __restrict__ b2g,
    float* __restrict__ outp)
{
    extern __shared__ char smraw[];
    unsigned short* sAh = (unsigned short*)(smraw);
    unsigned short* sAl = (unsigned short*)(smraw + 18432);
    unsigned short* sXh = (unsigned short*)(smraw + 36864);
    unsigned short* sXl = (unsigned short*)(smraw + 46080);
    unsigned short* sHh = (unsigned short*)(smraw + 55296);
    unsigned short* sHl = (unsigned short*)(smraw + 73728);
    float* sY  = (float*)(smraw + 92160);
    float* sb1 = (float*)(smraw + 109568);
    float* sb2 = sb1 + 128;
    float* slw = sb2 + 64;
    float* slb = slw + 64;
    float* smu = slb + 64;
    float* srs = smu + 64;

    uint32_t aH = smem_u32(sAh), aL = smem_u32(sAl);
    uint32_t xH = smem_u32(sXh), xL = smem_u32(sXl);
    uint32_t hH = smem_u32(sHh), hL = smem_u32(sHl);

    int b = blockIdx.y, p0 = blockIdx.x*64;
    int tid = threadIdx.x, w = tid>>5, lane = tid&31;
    int wc = (w>>1)*16, wpx = (w&1)*32;

    if (tid < 128) sb1[tid] = b1g[tid];
    if (tid < 64){ sb2[tid]=b2g[tid]; slw[tid]=lnw[tid]; slb[tid]=lnb[tid]; }

    // [M_id | M_ed] -> sA pitch 136
    const float* Mi = g_M + ((size_t)b*3+1)*4096;
    const float* Me = g_M + ((size_t)b*3+2)*4096;
    for (int i=tid;i<1024;i+=256){
        int r = i>>4, k4 = (i&15)*4;
        uint2 hh, ll;
        split4(*(const float4*)&Mi[r*64+k4], hh, ll);
        *(uint2*)&sAh[r*136+k4] = hh;    *(uint2*)&sAl[r*136+k4] = ll;
        split4(*(const float4*)&Me[r*64+k4], hh, ll);
        *(uint2*)&sAh[r*136+64+k4] = hh; *(uint2*)&sAl[r*136+64+k4] = ll;
    }
    // ni -> sX
    for (int i=tid;i<1024;i+=256){
        int c = i>>4, px4 = (i&15)*4;
        float4 v = *(const float4*)(g_ni + ((size_t)(b*C64+c))*HW + p0 + px4);
        uint2 hh, ll; split4(v, hh, ll);
        *(uint2*)&sXh[c*72+px4] = hh;
        *(uint2*)&sXl[c*72+px4] = ll;
    }
    __syncthreads();

    float acc[4][4];
    #pragma unroll
    for (int g=0;g<4;g++)
        #pragma unroll
        for (int k=0;k<4;k++) acc[g][k]=0.f;
    uint32_t offA = (uint32_t)(((wc+(lane&15))*136 + ((lane>>4)&1)*8)*2);
    uint32_t offB = (uint32_t)((((lane&7)+((lane>>3)&1)*8)*72 + ((lane>>4)&1)*8)*2);

    // pass A: M_id @ ni
    #pragma unroll
    for (int k16=0;k16<4;k16++){
        uint32_t Ah[4],Al[4];
        ldm_x4(Ah, aH + offA + k16*32);
        ldm_x4(Al, aL + offA + k16*32);
        #pragma unroll
        for (int hf=0;hf<2;hf++){
            uint32_t Bh[4],Bl[4];
            uint32_t ob = offB + (uint32_t)(k16*16*144 + (wpx+hf*16)*2);
            ldm_t4(Bh, xH + ob); ldm_t4(Bl, xL + ob);
            MMA3(acc[hf*2],   Ah, Al, Bh[0],Bh[1], Bl[0],Bl[1]);
            MMA3(acc[hf*2+1], Ah, Al, Bh[2],Bh[3], Bl[2],Bl[3]);
        }
    }
    __syncthreads();
    // ne -> sX
    for (int i=tid;i<1024;i+=256){
        int c = i>>4, px4 = (i&15)*4;
        float4 v = *(const float4*)(g_ne + ((size_t)(b*C64+c))*HW + p0 + px4);
        uint2 hh, ll; split4(v, hh, ll);
        *(uint2*)&sXh[c*72+px4] = hh;
        *(uint2*)&sXl[c*72+px4] = ll;
    }
    __syncthreads();
    // pass B: += M_ed @ ne  (A cols 64..127 -> +128 bytes)
    #pragma unroll
    for (int k16=0;k16<4;k16++){
        uint32_t Ah[4],Al[4];
        ldm_x4(Ah, aH + offA + 128 + k16*32);
        ldm_x4(Al, aL + offA + 128 + k16*32);
        #pragma unroll
        for (int hf=0;hf<2;hf++){
            uint32_t Bh[4],Bl[4];
            uint32_t ob = offB + (uint32_t)(k16*16*144 + (wpx+hf*16)*2);
            ldm_t4(Bh, xH + ob); ldm_t4(Bl, xL + ob);
            MMA3(acc[hf*2],   Ah, Al, Bh[0],Bh[1], Bl[0],Bl[1]);
            MMA3(acc[hf*2+1], Ah, Al, Bh[2],Bh[3], Bl[2],Bl[3]);
        }
    }
    {
        int c0 = wc + (lane>>2);
        int pxb = wpx + (lane&3)*2;
        #pragma unroll
        for (int g=0; g<4; g++){
            int px = pxb + g*8;
            *(float2*)&sY[c0*68+px]     = make_float2(acc[g][0], acc[g][1]);
            *(float2*)&sY[(c0+8)*68+px] = make_float2(acc[g][2], acc[g][3]);
        }
    }
    __syncthreads();
    apply_tail(sAh,sAl,sXh,sXl,sHh,sHl,sY,sb1,sb2,slw,slb,smu,srs,
               aH,aL,xH,xL,hH,hL, W1g, W2g, outp, b, p0);
}

// =====================================================================
extern "C" void kernel_launch(void* const* d_in, const int* in_sizes, int n_in,
                              void* d_out, int out_size)
{
    (void)in_sizes; (void)n_in; (void)out_size;
    const float* image  = (const float*)d_in[0];
    const float* event_ = (const float*)d_in[1];
    const float* Wq_c = (const float*)d_in[2];
    const float* Wk_c = (const float*)d_in[3];
    const float* Wv_c = (const float*)d_in[4];
    const float* temp_c = (const float*)d_in[5];
    const float* Wq_d = (const float*)d_in[6];
    const float* Wk_d = (const float*)d_in[7];
    const float* Wv_d = (const float*)d_in[8];
    const float* temp_d = (const float*)d_in[9];
    const float* ln_img_w = (const float*)d_in[10];
    const float* ln_img_b = (const float*)d_in[11];
    const float* ln_evt_w = (const float*)d_in[12];
    const float* ln_evt_b = (const float*)d_in[13];
    const float* ln_com_w = (const float*)d_in[14];
    const float* ln_com_b = (const float*)d_in[15];
    const float* ln_dif_w = (const float*)d_in[16];
    const float* ln_dif_b = (const float*)d_in[17];
    const float* ln1_w = (const float*)d_in[18];
    const float* ln1_b = (const float*)d_in[19];
    const float* ln2_w = (const float*)d_in[20];
    const float* ln2_b = (const float*)d_in[21];
    const float* fc1c_w = (const float*)d_in[22];
    const float* fc1c_b = (const float*)d_in[23];
    const float* fc2c_w = (const float*)d_in[24];
    const float* fc2c_b = (const float*)d_in[25];
    const float* fc1d_w = (const float*)d_in[26];
    const float* fc1d_b = (const float*)d_in[27];
    const float* fc2d_w = (const float*)d_in[28];
    const float* fc2d_b = (const float*)d_in[29];
    const float* proj1_w = (const float*)d_in[30];
    const float* proj2_w = (const float*)d_in[31];

    float* outc = (float*)d_out;
    float* outd = outc + (size_t)BATCH*C64*HW;

    const int SM3 = (4096*5 + 1024*2 + 64*3) * sizeof(float);

    cudaFuncSetAttribute(smallmath_kernel,    cudaFuncAttributeMaxDynamicSharedMemorySize, SM3);
    cudaFuncSetAttribute(apply_common_kernel, cudaFuncAttributeMaxDynamicSharedMemorySize, AP_SMEM_BYTES);
    cudaFuncSetAttribute(apply_diff_kernel,   cudaFuncAttributeMaxDynamicSharedMemorySize, AP_SMEM_BYTES);

    ln_kernel<<<BATCH*(HW/256), 256>>>(image, event_,
        ln_img_w, ln_img_b, ln_evt_w, ln_evt_b,
        ln_com_w, ln_com_b, ln_dif_w, ln_dif_b);

    dim3 g2(GK_KSPLIT, 4, BATCH);
    gram_mma_kernel<<<g2, 256>>>();

    smallmath_kernel<<<BATCH, 256, SM3>>>(Wq_c, Wk_c, Wv_c, temp_c,
                                          Wq_d, Wk_d, Wv_d, temp_d,
                                          proj1_w, proj2_w);

    dim3 g4(HW/64, BATCH);
    apply_common_kernel<<<g4, 256, AP_SMEM_BYTES>>>(ln1_w, ln1_b, fc1c_w, fc1c_b,
                                                    fc2c_w, fc2c_b, outc);
    apply_diff_kernel<<<g4, 256, AP_SMEM_BYTES>>>(ln2_w, ln2_b, fc1d_w, fc1d_b,
                                                  fc2d_w, fc2d_b, outd);
}

// round 9
// speedup vs baseline: 1.8732x; 1.4017x over previous
#include <cuda_runtime.h>
#include <cuda_bf16.h>
#include <math.h>
#include <stdint.h>

#define BATCH 4
#define C64   64
#define HW    65536
#define HEADS 4
#define HID   128
#define EPSF  1e-5f

#define TOT (BATCH*C64*HW)

// ---------------- scratch (device globals; no allocs) ----------------
// pre-split bf16 planes for [ni,ne,nc,nd] (tensor-major)
__device__ unsigned short g_hi[(size_t)4*TOT];
__device__ unsigned short g_lo[(size_t)4*TOT];
__device__ float g_gram256[BATCH*256*256];
// pre-split M (pitch 136): per batch: [0]=(Mc|Mc), [1]=(Mid|Med)
__device__ unsigned short g_Mh[BATCH*2*8704];
__device__ unsigned short g_Ml[BATCH*2*8704];
// pre-split weights: W1 pitch 72 (128 rows), W2 pitch 136 (64 rows); [0]=common,[1]=diff
__device__ unsigned short g_W1h[2*9216];
__device__ unsigned short g_W1l[2*9216];
__device__ unsigned short g_W2h[2*8704];
__device__ unsigned short g_W2l[2*8704];

// ======================= helpers ========================
__device__ __forceinline__ uint32_t smem_u32(const void* p){
    uint32_t a;
    asm("{ .reg .u64 t; cvta.to.shared.u64 t, %1; cvt.u32.u64 %0, t; }" : "=r"(a) : "l"(p));
    return a;
}
__device__ __forceinline__ void ldm_x4(uint32_t* r, uint32_t addr){
    asm volatile("ldmatrix.sync.aligned.m8n8.x4.shared.b16 {%0,%1,%2,%3}, [%4];"
        : "=r"(r[0]), "=r"(r[1]), "=r"(r[2]), "=r"(r[3]) : "r"(addr));
}
__device__ __forceinline__ void ldm_t4(uint32_t* r, uint32_t addr){
    asm volatile("ldmatrix.sync.aligned.m8n8.x4.trans.shared.b16 {%0,%1,%2,%3}, [%4];"
        : "=r"(r[0]), "=r"(r[1]), "=r"(r[2]), "=r"(r[3]) : "r"(addr));
}
__device__ __forceinline__ void mma_bf16(float& d0, float& d1, float& d2, float& d3,
        uint32_t a0, uint32_t a1, uint32_t a2, uint32_t a3,
        uint32_t b0, uint32_t b1){
    asm volatile("mma.sync.aligned.m16n8k16.row.col.f32.bf16.bf16.f32 "
        "{%0,%1,%2,%3}, {%4,%5,%6,%7}, {%8,%9}, {%0,%1,%2,%3};"
        : "+f"(d0), "+f"(d1), "+f"(d2), "+f"(d3)
        : "r"(a0), "r"(a1), "r"(a2), "r"(a3), "r"(b0), "r"(b1));
}
#define MMA3(ACC, AH, AL, BH0, BH1, BL0, BL1) do { \
    mma_bf16((ACC)[0],(ACC)[1],(ACC)[2],(ACC)[3], (AH)[0],(AH)[1],(AH)[2],(AH)[3], (BH0),(BH1)); \
    mma_bf16((ACC)[0],(ACC)[1],(ACC)[2],(ACC)[3], (AH)[0],(AH)[1],(AH)[2],(AH)[3], (BL0),(BL1)); \
    mma_bf16((ACC)[0],(ACC)[1],(ACC)[2],(ACC)[3], (AL)[0],(AL)[1],(AL)[2],(AL)[3], (BH0),(BH1)); \
} while(0)

__device__ __forceinline__ void split1(float a, unsigned short& h, unsigned short& l){
    __nv_bfloat16 hb = __float2bfloat16(a);
    float r = a - __bfloat162float(hb);
    h = __bfloat16_as_ushort(hb);
    l = __bfloat16_as_ushort(__float2bfloat16(r));
}
__device__ __forceinline__ void split2(float a, float b, uint32_t& h, uint32_t& l){
    __nv_bfloat16 ha=__float2bfloat16(a), hb=__float2bfloat16(b);
    float ra = a-__bfloat162float(ha), rb = b-__bfloat162float(hb);
    h = (uint32_t)__bfloat16_as_ushort(ha) | ((uint32_t)__bfloat16_as_ushort(hb)<<16);
    l = (uint32_t)__bfloat16_as_ushort(__float2bfloat16(ra))
      | ((uint32_t)__bfloat16_as_ushort(__float2bfloat16(rb))<<16);
}
__device__ __forceinline__ float gelu_f(float h){
    return 0.5f*h*(1.f + erff(h*0.70710678118654752f));
}

// =====================================================================
// K1: channel LayerNorm -> pre-split hi/lo planes (+ zero gram accum)
// grid: BATCH*(HW/512), block 256, 2 pixels/thread
// =====================================================================
__global__ void __launch_bounds__(256) ln_kernel(
    const float* __restrict__ img, const float* __restrict__ evt,
    const float* __restrict__ wi, const float* __restrict__ bi,
    const float* __restrict__ we, const float* __restrict__ be,
    const float* __restrict__ wc, const float* __restrict__ bc,
    const float* __restrict__ wd, const float* __restrict__ bd)
{
    if (blockIdx.x < 256) {
        int base = blockIdx.x * 1024 + threadIdx.x * 4;
        g_gram256[base+0] = 0.f; g_gram256[base+1] = 0.f;
        g_gram256[base+2] = 0.f; g_gram256[base+3] = 0.f;
    }
    int b  = blockIdx.x >> 7;                      // 128 blocks per batch
    int p  = ((blockIdx.x & 127) << 9) + threadIdx.x*2;
    const float* ip = img + (size_t)b*C64*HW + p;
    const float* ep = evt + (size_t)b*C64*HW + p;

    float si0=0,si1=0,se0=0,se1=0,sii0=0,sii1=0,see0=0,see1=0,sie0=0,sie1=0;
    #pragma unroll 8
    for (int c=0;c<C64;c++){
        float2 iv = *(const float2*)&ip[(size_t)c*HW];
        float2 ev = *(const float2*)&ep[(size_t)c*HW];
        si0+=iv.x; si1+=iv.y; se0+=ev.x; se1+=ev.y;
        sii0+=iv.x*iv.x; sii1+=iv.y*iv.y;
        see0+=ev.x*ev.x; see1+=ev.y*ev.y;
        sie0+=iv.x*ev.x; sie1+=iv.y*ev.y;
    }
    const float inv64 = 1.f/64.f;
    float mi0=si0*inv64, mi1=si1*inv64, me0=se0*inv64, me1=se1*inv64;
    float mc0=(si0+se0)*inv64, mc1=(si1+se1)*inv64;
    float md0=(si0-se0)*inv64, md1=(si1-se1)*inv64;
    float ri0=rsqrtf(sii0*inv64-mi0*mi0+EPSF), ri1=rsqrtf(sii1*inv64-mi1*mi1+EPSF);
    float re0=rsqrtf(see0*inv64-me0*me0+EPSF), re1=rsqrtf(see1*inv64-me1*me1+EPSF);
    float rc0=rsqrtf((sii0+2.f*sie0+see0)*inv64-mc0*mc0+EPSF);
    float rc1=rsqrtf((sii1+2.f*sie1+see1)*inv64-mc1*mc1+EPSF);
    float rd0=rsqrtf((sii0-2.f*sie0+see0)*inv64-md0*md0+EPSF);
    float rd1=rsqrtf((sii1-2.f*sie1+see1)*inv64-md1*md1+EPSF);

    size_t ob = (size_t)b*C64*HW + p;
    #pragma unroll 4
    for (int c=0;c<C64;c++){
        float2 iv = *(const float2*)&ip[(size_t)c*HW];
        float2 ev = *(const float2*)&ep[(size_t)c*HW];
        size_t o = ob + (size_t)c*HW;
        uint32_t hh, ll;
        // ni
        split2((iv.x-mi0)*ri0*wi[c]+bi[c], (iv.y-mi1)*ri1*wi[c]+bi[c], hh, ll);
        *(uint32_t*)&g_hi[o] = hh; *(uint32_t*)&g_lo[o] = ll;
        // ne
        split2((ev.x-me0)*re0*we[c]+be[c], (ev.y-me1)*re1*we[c]+be[c], hh, ll);
        *(uint32_t*)&g_hi[(size_t)TOT + o] = hh; *(uint32_t*)&g_lo[(size_t)TOT + o] = ll;
        // nc
        split2((iv.x+ev.x-mc0)*rc0*wc[c]+bc[c], (iv.y+ev.y-mc1)*rc1*wc[c]+bc[c], hh, ll);
        *(uint32_t*)&g_hi[(size_t)2*TOT + o] = hh; *(uint32_t*)&g_lo[(size_t)2*TOT + o] = ll;
        // nd
        split2((iv.x-ev.x-md0)*rd0*wd[c]+bd[c], (iv.y-ev.y-md1)*rd1*wd[c]+bd[c], hh, ll);
        *(uint32_t*)&g_hi[(size_t)3*TOT + o] = hh; *(uint32_t*)&g_lo[(size_t)3*TOT + o] = ll;
    }
}

// =====================================================================
// K2: stacked Gram via mma.sync bf16 hi/lo (3 passes), fp32 accum.
// Loader is now a pure uint4 copy from pre-split planes.
// =====================================================================
#define GK_KSPLIT 32
#define GK_KRANGE (HW/GK_KSPLIT)
#define GK_KC     32
#define GK_NCH    (GK_KRANGE/GK_KC)
#define SPITCH    40

__global__ void __launch_bounds__(256) gram_mma_kernel()
{
    __shared__ __align__(16) unsigned short sAhi[128*SPITCH];
    __shared__ __align__(16) unsigned short sAlo[128*SPITCH];
    __shared__ __align__(16) unsigned short sBhi[128*SPITCH];
    __shared__ __align__(16) unsigned short sBlo[128*SPITCH];

    int tid = threadIdx.x;
    int wid = tid >> 5, lane = tid & 31;
    int ks = blockIdx.x, tileid = blockIdx.y, b = blockIdx.z;
    int m0 = (tileid >> 1) * 128;
    int n0 = (tileid & 1) * 128;
    int warp_m = (wid >> 1) * 32;
    int warp_n = (wid & 1) * 64;

    int lr = tid >> 1;
    int lc = (tid & 1) * 16;
    size_t offA_g = (size_t)((m0+lr)>>6)*TOT + ((size_t)(b*C64)+((m0+lr)&63))*HW + (size_t)ks*GK_KRANGE + lc;
    size_t offB_g = (size_t)((n0+lr)>>6)*TOT + ((size_t)(b*C64)+((n0+lr)&63))*HW + (size_t)ks*GK_KRANGE + lc;
    const unsigned short* sAg_h = g_hi + offA_g;
    const unsigned short* sAg_l = g_lo + offA_g;
    const unsigned short* sBg_h = g_hi + offB_g;
    const unsigned short* sBg_l = g_lo + offB_g;

    uint32_t aHi = smem_u32(sAhi), aLo = smem_u32(sAlo);
    uint32_t bHi = smem_u32(sBhi), bLo = smem_u32(sBlo);

    int rowA = warp_m + (lane & 15);
    int colA = (lane >> 4) * 8;
    uint32_t offA = (uint32_t)(rowA*SPITCH + colA) * 2;
    int rowB = warp_n + (lane & 7) + ((lane >> 4) & 1) * 8;
    int colB = ((lane >> 3) & 1) * 8;
    uint32_t offB = (uint32_t)(rowB*SPITCH + colB) * 2;

    float acc[2][8][4];
    #pragma unroll
    for (int i=0;i<2;i++)
        #pragma unroll
        for (int j=0;j<8;j++)
            #pragma unroll
            for (int k=0;k<4;k++) acc[i][j][k] = 0.f;

    unsigned short* dAh = sAhi + lr*SPITCH + lc;
    unsigned short* dAl = sAlo + lr*SPITCH + lc;
    unsigned short* dBh = sBhi + lr*SPITCH + lc;
    unsigned short* dBl = sBlo + lr*SPITCH + lc;

    for (int t = 0; t < GK_NCH; t++) {
        __syncthreads();
        int kc = t * GK_KC;
        // pure copy: 16 shorts per matrix per thread (2 uint4 each)
        *(uint4*)&dAh[0] = *(const uint4*)&sAg_h[kc];
        *(uint4*)&dAh[8] = *(const uint4*)&sAg_h[kc+8];
        *(uint4*)&dAl[0] = *(const uint4*)&sAg_l[kc];
        *(uint4*)&dAl[8] = *(const uint4*)&sAg_l[kc+8];
        *(uint4*)&dBh[0] = *(const uint4*)&sBg_h[kc];
        *(uint4*)&dBh[8] = *(const uint4*)&sBg_h[kc+8];
        *(uint4*)&dBl[0] = *(const uint4*)&sBg_l[kc];
        *(uint4*)&dBl[8] = *(const uint4*)&sBg_l[kc+8];
        __syncthreads();
        #pragma unroll
        for (int k16 = 0; k16 < GK_KC; k16 += 16) {
            uint32_t kb = (uint32_t)(k16 * 2);
            uint32_t Ah0[4], Ah1[4], Al0[4], Al1[4];
            ldm_x4(Ah0, aHi + offA + kb);
            ldm_x4(Ah1, aHi + offA + kb + 16*SPITCH*2);
            ldm_x4(Al0, aLo + offA + kb);
            ldm_x4(Al1, aLo + offA + kb + 16*SPITCH*2);
            #pragma unroll
            for (int np = 0; np < 4; np++) {
                uint32_t Bh[4], Bl[4];
                uint32_t ob = offB + kb + (uint32_t)(np*16*SPITCH*2);
                ldm_x4(Bh, bHi + ob);
                ldm_x4(Bl, bLo + ob);
                int n2 = np*2;
                MMA3(acc[0][n2],   Ah0, Al0, Bh[0],Bh[1], Bl[0],Bl[1]);
                MMA3(acc[0][n2+1], Ah0, Al0, Bh[2],Bh[3], Bl[2],Bl[3]);
                MMA3(acc[1][n2],   Ah1, Al1, Bh[0],Bh[1], Bl[0],Bl[1]);
                MMA3(acc[1][n2+1], Ah1, Al1, Bh[2],Bh[3], Bl[2],Bl[3]);
            }
        }
    }

    float* G = g_gram256 + (size_t)b*65536;
    int rbase = m0 + warp_m + (lane >> 2);
    int cbase = n0 + warp_n + (lane & 3)*2;
    #pragma unroll
    for (int i=0;i<2;i++){
        #pragma unroll
        for (int ns=0;ns<8;ns++){
            int rr = rbase + i*16;
            int cc = cbase + ns*8;
            atomicAdd(&G[rr*256 + cc],       acc[i][ns][0]);
            atomicAdd(&G[rr*256 + cc + 1],   acc[i][ns][1]);
            atomicAdd(&G[(rr+8)*256 + cc],   acc[i][ns][2]);
            atomicAdd(&G[(rr+8)*256 + cc+1], acc[i][ns][3]);
        }
    }
}

// =====================================================================
// K3: tiny per-batch math -> pre-split M buffers + pre-split weights.
// =====================================================================
__device__ __forceinline__ void ld_mat(float* s, const float* __restrict__ g, int tid){
    for (int i=tid; i<4096; i+=256) s[i] = g[i];
}
__device__ __forceinline__ void ld_matg(float* s, const float* __restrict__ g, int tid){
    for (int i=tid; i<4096; i+=256) s[i] = g[(i>>6)*256 + (i&63)];
}
__device__ __forceinline__ void mm64_nn(float* Cm, const float* A, const float* Bm, int tid){
    int ty = tid>>4, tx = tid&15;
    float acc[4][4] = {};
    for (int k=0;k<64;k++){
        float4 bv = *(const float4*)&Bm[k*64 + tx*4];
        float b4[4] = {bv.x,bv.y,bv.z,bv.w};
        #pragma unroll
        for (int ii=0;ii<4;ii++){
            float a = A[(ty*4+ii)*64 + k];
            #pragma unroll
            for (int jj=0;jj<4;jj++) acc[ii][jj] += a*b4[jj];
        }
    }
    #pragma unroll
    for (int ii=0;ii<4;ii++)
        #pragma unroll
        for (int jj=0;jj<4;jj++)
            Cm[(ty*4+ii)*64 + tx*4+jj] = acc[ii][jj];
    __syncthreads();
}
__device__ __forceinline__ void mm64_nt(float* Cm, const float* A, const float* Bm, int tid){
    int ty = tid>>4, tx = tid&15;
    float acc[4][4] = {};
    for (int k=0;k<64;k++){
        float a4[4], b4[4];
        #pragma unroll
        for (int ii=0;ii<4;ii++) a4[ii] = A[(ty*4+ii)*64 + k];
        #pragma unroll
        for (int jj=0;jj<4;jj++) b4[jj] = Bm[(tx*4+jj)*64 + k];
        #pragma unroll
        for (int ii=0;ii<4;ii++)
            #pragma unroll
            for (int jj=0;jj<4;jj++) acc[ii][jj] += a4[ii]*b4[jj];
    }
    #pragma unroll
    for (int ii=0;ii<4;ii++)
        #pragma unroll
        for (int jj=0;jj<4;jj++)
            Cm[(ty*4+ii)*64 + tx*4+jj] = acc[ii][jj];
    __syncthreads();
}
__device__ __forceinline__ void rownorm_inv(float* inv, const float* T, const float* Wm, int tid){
    if (tid < 64){
        float s = 0.f;
        for (int k=0;k<64;k++) s += T[tid*64+k]*Wm[tid*64+k];
        inv[tid] = 1.f / fmaxf(sqrtf(fmaxf(s, 0.f)), 1e-12f);
    }
    __syncthreads();
}
__device__ __forceinline__ void attn_softmax(float* out, const float* raw,
        const float* invq, const float* invk, const float* __restrict__ temp, int tid){
    if (tid < 64){
        int head = tid >> 4, base = head*16;
        float t = temp[head];
        float l[16]; float mx = -1e30f;
        #pragma unroll
        for (int s=0;s<16;s++){
            l[s] = raw[tid*64 + base + s] * invq[tid] * invk[base+s] * t;
            mx = fmaxf(mx, l[s]);
        }
        float sum = 0.f;
        #pragma unroll
        for (int s=0;s<16;s++){ l[s] = expf(l[s]-mx); sum += l[s]; }
        float r = 1.f/sum;
        #pragma unroll
        for (int s=0;s<16;s++) out[tid*16+s] = l[s]*r;
    }
    __syncthreads();
}
__device__ __forceinline__ void bdv(float* Cm, const float* at, const float* Wv, int tid){
    int ty = tid>>4, tx = tid&15;
    float acc[4][4] = {};
    for (int s=0;s<16;s++){
        #pragma unroll
        for (int ii=0;ii<4;ii++){
            int row = ty*4+ii; int head = row >> 4;
            float a = at[row*16 + s];
            float4 wv = *(const float4*)&Wv[(head*16+s)*64 + tx*4];
            acc[ii][0] += a*wv.x; acc[ii][1] += a*wv.y;
            acc[ii][2] += a*wv.z; acc[ii][3] += a*wv.w;
        }
    }
    #pragma unroll
    for (int ii=0;ii<4;ii++)
        #pragma unroll
        for (int jj=0;jj<4;jj++)
            Cm[(ty*4+ii)*64 + tx*4+jj] = acc[ii][jj];
    __syncthreads();
}
// store a 64x64 M into one half of a pitched split buffer
__device__ __forceinline__ void store_M_half(const float* sR, int b, int buf, int half, int tid){
    size_t base = ((size_t)b*2+buf)*8704;
    for (int i=tid;i<4096;i+=256){
        int r=i>>6, k=i&63;
        unsigned short h,l; split1(sR[i],h,l);
        g_Mh[base + r*136 + half*64 + k] = h;
        g_Ml[base + r*136 + half*64 + k] = l;
    }
    __syncthreads();
}

__global__ void __launch_bounds__(256) smallmath_kernel(
    const float* __restrict__ Wq_c, const float* __restrict__ Wk_c, const float* __restrict__ Wv_c,
    const float* __restrict__ temp_c,
    const float* __restrict__ Wq_d, const float* __restrict__ Wk_d, const float* __restrict__ Wv_d,
    const float* __restrict__ temp_d,
    const float* __restrict__ proj1, const float* __restrict__ proj2,
    const float* __restrict__ fc1c_w, const float* __restrict__ fc2c_w,
    const float* __restrict__ fc1d_w, const float* __restrict__ fc2d_w)
{
    extern __shared__ float sm[];
    float* sA   = sm;
    float* sB   = sA + 4096;
    float* sG   = sB + 4096;
    float* sT   = sG + 4096;
    float* sR   = sT + 4096;
    float* aA   = sR + 4096;
    float* aB   = aA + 1024;
    float* invq  = aB + 1024;
    float* invk1 = invq + 64;
    float* invk2 = invk1 + 64;

    int b = blockIdx.x;
    int tid = threadIdx.x;

    // block 0 pre-splits FFN weights
    if (b == 0){
        for (int i=tid;i<8192;i+=256){
            int r=i>>6, k=i&63;
            unsigned short h,l;
            split1(fc1c_w[i],h,l); g_W1h[r*72+k]=h; g_W1l[r*72+k]=l;
            split1(fc1d_w[i],h,l); g_W1h[9216+r*72+k]=h; g_W1l[9216+r*72+k]=l;
        }
        for (int i=tid;i<8192;i+=256){
            int r=i>>7, k=i&127;
            unsigned short h,l;
            split1(fc2c_w[i],h,l); g_W2h[r*136+k]=h; g_W2l[r*136+k]=l;
            split1(fc2d_w[i],h,l); g_W2h[8704+r*136+k]=h; g_W2l[8704+r*136+k]=l;
        }
    }

    #define GB(bi,bj) (g_gram256 + (size_t)b*65536 + (bi)*64*256 + (bj)*64)

    // ---------- common branch ----------
    ld_mat(sA, Wq_c, tid); ld_matg(sG, GB(2,2), tid); __syncthreads();
    mm64_nn(sT, sA, sG, tid);
    rownorm_inv(invq, sT, sA, tid);
    ld_mat(sB, Wk_c, tid); ld_matg(sG, GB(0,0), tid); __syncthreads();
    mm64_nn(sT, sB, sG, tid);
    rownorm_inv(invk1, sT, sB, tid);
    ld_matg(sG, GB(1,1), tid); __syncthreads();
    mm64_nn(sT, sB, sG, tid);
    rownorm_inv(invk2, sT, sB, tid);
    ld_matg(sG, GB(2,0), tid); __syncthreads();
    mm64_nn(sT, sA, sG, tid);
    mm64_nt(sR, sT, sB, tid);
    attn_softmax(aA, sR, invq, invk1, temp_c, tid);
    ld_matg(sG, GB(2,1), tid); __syncthreads();
    mm64_nn(sT, sA, sG, tid);
    mm64_nt(sR, sT, sB, tid);
    attn_softmax(aB, sR, invq, invk2, temp_c, tid);
    if (tid < 64){
        #pragma unroll
        for (int s=0;s<16;s++) aA[tid*16+s] *= aB[tid*16+s];
    }
    __syncthreads();
    ld_mat(sB, Wv_c, tid); __syncthreads();
    bdv(sT, aA, sB, tid);
    ld_mat(sA, proj1, tid); __syncthreads();
    mm64_nn(sR, sA, sT, tid);
    store_M_half(sR, b, 0, 0, tid);
    store_M_half(sR, b, 0, 1, tid);

    // ---------- differential branch ----------
    ld_mat(sA, Wq_d, tid); ld_matg(sG, GB(3,3), tid); __syncthreads();
    mm64_nn(sT, sA, sG, tid);
    rownorm_inv(invq, sT, sA, tid);
    ld_mat(sB, Wk_d, tid); ld_matg(sG, GB(0,0), tid); __syncthreads();
    mm64_nn(sT, sB, sG, tid);
    rownorm_inv(invk1, sT, sB, tid);
    ld_matg(sG, GB(1,1), tid); __syncthreads();
    mm64_nn(sT, sB, sG, tid);
    rownorm_inv(invk2, sT, sB, tid);
    ld_matg(sG, GB(3,0), tid); __syncthreads();
    mm64_nn(sT, sA, sG, tid);
    mm64_nt(sR, sT, sB, tid);
    attn_softmax(aA, sR, invq, invk1, temp_d, tid);
    ld_matg(sG, GB(3,1), tid); __syncthreads();
    mm64_nn(sT, sA, sG, tid);
    mm64_nt(sR, sT, sB, tid);
    attn_softmax(aB, sR, invq, invk2, temp_d, tid);
    ld_mat(sB, Wv_d, tid); ld_mat(sA, proj2, tid); __syncthreads();
    bdv(sT, aA, sB, tid);
    mm64_nn(sR, sA, sT, tid);
    store_M_half(sR, b, 1, 0, tid);
    bdv(sT, aB, sB, tid);
    mm64_nn(sR, sA, sT, tid);
    store_M_half(sR, b, 1, 1, tid);
    #undef GB
}

// =====================================================================
// K4: unified apply kernel (common: msel=0 (Mc|Mc); diff: msel=1 (Mid|Med))
// Y = M1@ni + M2@ne ; LN ; FFN ; residual. All MMA operands pre-split.
// smem byte layout identical to R8.
// =====================================================================
#define AP_SMEM_BYTES 111616

__global__ void __launch_bounds__(256) apply_kernel(
    int msel, int widx,
    const float* __restrict__ lnw, const float* __restrict__ lnb,
    const float* __restrict__ b1g, const float* __restrict__ b2g,
    float* __restrict__ outp)
{
    extern __shared__ char smraw[];
    unsigned short* sAh = (unsigned short*)(smraw);
    unsigned short* sAl = (unsigned short*)(smraw + 18432);
    unsigned short* sXh = (unsigned short*)(smraw + 36864);
    unsigned short* sXl = (unsigned short*)(smraw + 46080);
    unsigned short* sHh = (unsigned short*)(smraw + 55296);
    unsigned short* sHl = (unsigned short*)(smraw + 73728);
    float* sY  = (float*)(smraw + 92160);
    float* sb1 = (float*)(smraw + 109568);
    float* sb2 = sb1 + 128;
    float* slw = sb2 + 64;
    float* slb = slw + 64;
    float* smu = slb + 64;
    float* srs = smu + 64;

    uint32_t aH = smem_u32(sAh), aL = smem_u32(sAl);
    uint32_t xH = smem_u32(sXh), xL = smem_u32(sXl);
    uint32_t hH = smem_u32(sHh), hL = smem_u32(sHl);

    int b = blockIdx.y, p0 = blockIdx.x*64;
    int tid = threadIdx.x, w = tid>>5, lane = tid&31;
    int wc = (w>>1)*16, wpx = (w&1)*32;

    if (tid < 128) sb1[tid] = b1g[tid];
    if (tid < 64){ sb2[tid]=b2g[tid]; slw[tid]=lnw[tid]; slb[tid]=lnb[tid]; }

    // M copy (pre-split, pitch 136): 1088 uint4 per plane
    {
        const uint4* mh = (const uint4*)&g_Mh[((size_t)b*2+msel)*8704];
        const uint4* ml = (const uint4*)&g_Ml[((size_t)b*2+msel)*8704];
        uint4* dh = (uint4*)sAh; uint4* dl = (uint4*)sAl;
        for (int i=tid;i<1088;i+=256){ dh[i]=mh[i]; dl[i]=ml[i]; }
    }
    // ni planes -> sX (pure copy)
    for (int i=tid;i<512;i+=256){
        int c=i>>3, q=i&7;
        size_t off = ((size_t)(b*C64+c))*HW + p0 + q*8;
        *(uint4*)&sXh[c*72 + q*8] = *(const uint4*)&g_hi[off];
        *(uint4*)&sXl[c*72 + q*8] = *(const uint4*)&g_lo[off];
    }
    __syncthreads();

    float acc[4][4];
    #pragma unroll
    for (int g=0;g<4;g++)
        #pragma unroll
        for (int k=0;k<4;k++) acc[g][k]=0.f;
    uint32_t offA = (uint32_t)(((wc+(lane&15))*136 + ((lane>>4)&1)*8)*2);
    uint32_t offB = (uint32_t)((((lane&7)+((lane>>3)&1)*8)*72 + ((lane>>4)&1)*8)*2);

    // pass A: M1 @ ni
    #pragma unroll
    for (int k16=0;k16<4;k16++){
        uint32_t Ah[4],Al[4];
        ldm_x4(Ah, aH + offA + k16*32);
        ldm_x4(Al, aL + offA + k16*32);
        #pragma unroll
        for (int hf=0;hf<2;hf++){
            uint32_t Bh[4],Bl[4];
            uint32_t ob = offB + (uint32_t)(k16*16*144 + (wpx+hf*16)*2);
            ldm_t4(Bh, xH + ob); ldm_t4(Bl, xL + ob);
            MMA3(acc[hf*2],   Ah, Al, Bh[0],Bh[1], Bl[0],Bl[1]);
            MMA3(acc[hf*2+1], Ah, Al, Bh[2],Bh[3], Bl[2],Bl[3]);
        }
    }
    __syncthreads();
    // ne planes -> sX
    for (int i=tid;i<512;i+=256){
        int c=i>>3, q=i&7;
        size_t off = (size_t)TOT + ((size_t)(b*C64+c))*HW + p0 + q*8;
        *(uint4*)&sXh[c*72 + q*8] = *(const uint4*)&g_hi[off];
        *(uint4*)&sXl[c*72 + q*8] = *(const uint4*)&g_lo[off];
    }
    __syncthreads();
    // pass B: += M2 @ ne  (A cols 64..127 -> +128 bytes)
    #pragma unroll
    for (int k16=0;k16<4;k16++){
        uint32_t Ah[4],Al[4];
        ldm_x4(Ah, aH + offA + 128 + k16*32);
        ldm_x4(Al, aL + offA + 128 + k16*32);
        #pragma unroll
        for (int hf=0;hf<2;hf++){
            uint32_t Bh[4],Bl[4];
            uint32_t ob = offB + (uint32_t)(k16*16*144 + (wpx+hf*16)*2);
            ldm_t4(Bh, xH + ob); ldm_t4(Bl, xL + ob);
            MMA3(acc[hf*2],   Ah, Al, Bh[0],Bh[1], Bl[0],Bl[1]);
            MMA3(acc[hf*2+1], Ah, Al, Bh[2],Bh[3], Bl[2],Bl[3]);
        }
    }
    {
        int c0 = wc + (lane>>2);
        int pxb = wpx + (lane&3)*2;
        #pragma unroll
        for (int g=0; g<4; g++){
            int px = pxb + g*8;
            *(float2*)&sY[c0*68+px]     = make_float2(acc[g][0], acc[g][1]);
            *(float2*)&sY[(c0+8)*68+px] = make_float2(acc[g][2], acc[g][3]);
        }
    }
    __syncthreads();

    // ---------------- tail: LN -> FFN -> residual ----------------
    if (tid < 64){
        float s=0.f, ss=0.f;
        for (int c=0;c<64;c++){ float v = sY[c*68+tid]; s += v; ss += v*v; }
        float mu = s*(1.f/64.f);
        float var = ss*(1.f/64.f) - mu*mu;
        smu[tid] = mu; srs[tid] = rsqrtf(var + EPSF);
    }
    __syncthreads();
    // Z -> sX (hi/lo split), W1 copy (pre-split, pitch 72, 1152 uint4)
    for (int i=tid;i<2048;i+=256){
        int c = i>>5, px = (i&31)*2;
        float z0 = (sY[c*68+px  ]-smu[px  ])*srs[px  ]*slw[c] + slb[c];
        float z1 = (sY[c*68+px+1]-smu[px+1])*srs[px+1]*slw[c] + slb[c];
        uint32_t hh, ll; split2(z0, z1, hh, ll);
        *(uint32_t*)&sXh[c*72+px] = hh;
        *(uint32_t*)&sXl[c*72+px] = ll;
    }
    {
        const uint4* wh = (const uint4*)&g_W1h[widx*9216];
        const uint4* wl = (const uint4*)&g_W1l[widx*9216];
        uint4* dh = (uint4*)sAh; uint4* dl = (uint4*)sAl;
        for (int i=tid;i<1152;i+=256){ dh[i]=wh[i]; dl[i]=wl[i]; }
    }
    __syncthreads();

    // GEMM2: H[128h x 64px] = W1 @ Z, warp tile 32h x 32px
    {
        int wh_ = (w>>1)*32;
        float a2[2][4][4];
        #pragma unroll
        for (int m=0;m<2;m++)
            #pragma unroll
            for (int g=0;g<4;g++)
                #pragma unroll
                for (int k=0;k<4;k++) a2[m][g][k]=0.f;
        uint32_t offA2 = (uint32_t)(((wh_+(lane&15))*72 + ((lane>>4)&1)*8)*2);
        #pragma unroll
        for (int k16=0;k16<4;k16++){
            uint32_t Ah0[4],Al0[4],Ah1[4],Al1[4];
            ldm_x4(Ah0, aH + offA2 + k16*32);
            ldm_x4(Al0, aL + offA2 + k16*32);
            ldm_x4(Ah1, aH + offA2 + k16*32 + 16*144);
            ldm_x4(Al1, aL + offA2 + k16*32 + 16*144);
            #pragma unroll
            for (int hf=0;hf<2;hf++){
                uint32_t Bh[4],Bl[4];
                uint32_t ob = offB + (uint32_t)(k16*16*144 + (wpx+hf*16)*2);
                ldm_t4(Bh, xH + ob); ldm_t4(Bl, xL + ob);
                int g0=hf*2, g1=hf*2+1;
                MMA3(a2[0][g0], Ah0, Al0, Bh[0],Bh[1], Bl[0],Bl[1]);
                MMA3(a2[0][g1], Ah0, Al0, Bh[2],Bh[3], Bl[2],Bl[3]);
                MMA3(a2[1][g0], Ah1, Al1, Bh[0],Bh[1], Bl[0],Bl[1]);
                MMA3(a2[1][g1], Ah1, Al1, Bh[2],Bh[3], Bl[2],Bl[3]);
            }
        }
        int hb = wh_ + (lane>>2);
        int pxb = wpx + (lane&3)*2;
        #pragma unroll
        for (int m=0;m<2;m++){
            int r0 = hb + m*16, r1 = r0 + 8;
            float bb0 = sb1[r0], bb1 = sb1[r1];
            #pragma unroll
            for (int g=0; g<4; g++){
                int px = pxb + g*8;
                float v0 = gelu_f(a2[m][g][0] + bb0);
                float v1 = gelu_f(a2[m][g][1] + bb0);
                float v2 = gelu_f(a2[m][g][2] + bb1);
                float v3 = gelu_f(a2[m][g][3] + bb1);
                uint32_t hh, ll;
                split2(v0, v1, hh, ll);
                *(uint32_t*)&sHh[r0*72+px] = hh; *(uint32_t*)&sHl[r0*72+px] = ll;
                split2(v2, v3, hh, ll);
                *(uint32_t*)&sHh[r1*72+px] = hh; *(uint32_t*)&sHl[r1*72+px] = ll;
            }
        }
    }
    __syncthreads();
    // W2 copy (pre-split, pitch 136, 1088 uint4)
    {
        const uint4* wh = (const uint4*)&g_W2h[widx*8704];
        const uint4* wl = (const uint4*)&g_W2l[widx*8704];
        uint4* dh = (uint4*)sAh; uint4* dl = (uint4*)sAl;
        for (int i=tid;i<1088;i+=256){ dh[i]=wh[i]; dl[i]=wl[i]; }
    }
    __syncthreads();

    // GEMM3: O[64c x 64px] = W2 @ H (k=128), + bias + residual + store
    {
        float a3[4][4];
        #pragma unroll
        for (int g=0;g<4;g++)
            #pragma unroll
            for (int k=0;k<4;k++) a3[g][k]=0.f;
        uint32_t offA3 = (uint32_t)(((wc+(lane&15))*136 + ((lane>>4)&1)*8)*2);
        #pragma unroll
        for (int k16=0;k16<8;k16++){
            uint32_t Ah[4],Al[4];
            ldm_x4(Ah, aH + offA3 + k16*32);
            ldm_x4(Al, aL + offA3 + k16*32);
            #pragma unroll
            for (int hf=0;hf<2;hf++){
                uint32_t Bh[4],Bl[4];
                uint32_t ob = offB + (uint32_t)(k16*16*144 + (wpx+hf*16)*2);
                ldm_t4(Bh, hH + ob); ldm_t4(Bl, hL + ob);
                MMA3(a3[hf*2],   Ah, Al, Bh[0],Bh[1], Bl[0],Bl[1]);
                MMA3(a3[hf*2+1], Ah, Al, Bh[2],Bh[3], Bl[2],Bl[3]);
            }
        }
        int c0 = wc + (lane>>2);
        int pxb = wpx + (lane&3)*2;
        float bc0 = sb2[c0], bc1 = sb2[c0+8];
        #pragma unroll
        for (int g=0; g<4; g++){
            int px = pxb + g*8;
            float2 o;
            o.x = a3[g][0] + bc0 + sY[c0*68+px];
            o.y = a3[g][1] + bc0 + sY[c0*68+px+1];
            *(float2*)&outp[((size_t)(b*C64+c0))*HW + p0 + px] = o;
            o.x = a3[g][2] + bc1 + sY[(c0+8)*68+px];
            o.y = a3[g][3] + bc1 + sY[(c0+8)*68+px+1];
            *(float2*)&outp[((size_t)(b*C64+c0+8))*HW + p0 + px] = o;
        }
    }
}

// =====================================================================
extern "C" void kernel_launch(void* const* d_in, const int* in_sizes, int n_in,
                              void* d_out, int out_size)
{
    (void)in_sizes; (void)n_in; (void)out_size;
    const float* image  = (const float*)d_in[0];
    const float* event_ = (const float*)d_in[1];
    const float* Wq_c = (const float*)d_in[2];
    const float* Wk_c = (const float*)d_in[3];
    const float* Wv_c = (const float*)d_in[4];
    const float* temp_c = (const float*)d_in[5];
    const float* Wq_d = (const float*)d_in[6];
    const float* Wk_d = (const float*)d_in[7];
    const float* Wv_d = (const float*)d_in[8];
    const float* temp_d = (const float*)d_in[9];
    const float* ln_img_w = (const float*)d_in[10];
    const float* ln_img_b = (const float*)d_in[11];
    const float* ln_evt_w = (const float*)d_in[12];
    const float* ln_evt_b = (const float*)d_in[13];
    const float* ln_com_w = (const float*)d_in[14];
    const float* ln_com_b = (const float*)d_in[15];
    const float* ln_dif_w = (const float*)d_in[16];
    const float* ln_dif_b = (const float*)d_in[17];
    const float* ln1_w = (const float*)d_in[18];
    const float* ln1_b = (const float*)d_in[19];
    const float* ln2_w = (const float*)d_in[20];
    const float* ln2_b = (const float*)d_in[21];
    const float* fc1c_w = (const float*)d_in[22];
    const float* fc1c_b = (const float*)d_in[23];
    const float* fc2c_w = (const float*)d_in[24];
    const float* fc2c_b = (const float*)d_in[25];
    const float* fc1d_w = (const float*)d_in[26];
    const float* fc1d_b = (const float*)d_in[27];
    const float* fc2d_w = (const float*)d_in[28];
    const float* fc2d_b = (const float*)d_in[29];
    const float* proj1_w = (const float*)d_in[30];
    const float* proj2_w = (const float*)d_in[31];

    float* outc = (float*)d_out;
    float* outd = outc + (size_t)BATCH*C64*HW;

    const int SM3 = (4096*5 + 1024*2 + 64*3) * sizeof(float);

    cudaFuncSetAttribute(smallmath_kernel, cudaFuncAttributeMaxDynamicSharedMemorySize, SM3);
    cudaFuncSetAttribute(apply_kernel,     cudaFuncAttributeMaxDynamicSharedMemorySize, AP_SMEM_BYTES);

    ln_kernel<<<BATCH*(HW/512), 256>>>(image, event_,
        ln_img_w, ln_img_b, ln_evt_w, ln_evt_b,
        ln_com_w, ln_com_b, ln_dif_w, ln_dif_b);

    dim3 g2(GK_KSPLIT, 4, BATCH);
    gram_mma_kernel<<<g2, 256>>>();

    smallmath_kernel<<<BATCH, 256, SM3>>>(Wq_c, Wk_c, Wv_c, temp_c,
                                          Wq_d, Wk_d, Wv_d, temp_d,
                                          proj1_w, proj2_w,
                                          fc1c_w, fc2c_w, fc1d_w, fc2d_w);

    dim3 g4(HW/64, BATCH);
    apply_kernel<<<g4, 256, AP_SMEM_BYTES>>>(0, 0, ln1_w, ln1_b, fc1c_b, fc2c_b, outc);
    apply_kernel<<<g4, 256, AP_SMEM_BYTES>>>(1, 1, ln2_w, ln2_b, fc1d_b, fc2d_b, outd);
}